// round 2
// baseline (speedup 1.0000x reference)
#include <cuda_runtime.h>
#include <math.h>
#include <stdint.h>

#define NB 8192
#define ND 2048
#define NH 512
#define NA 3
#define LNEPS 1e-5f
#define SQRT_D 45.25483399593904f

typedef unsigned long long ull;

// ---------------- scratch (device globals; no allocation allowed) ----------
__device__ float g_h1[(size_t)NB * NH];
__device__ float g_h2[(size_t)NB * (NH / 2)];
__device__ float g_gf[(size_t)NB * ND];
__device__ float g_q[(size_t)NB * ND];
__device__ float g_k1[(size_t)NB * ND];
__device__ float g_k2[(size_t)NB * ND];
__device__ float g_v1[(size_t)NB * ND];
__device__ float g_v2[(size_t)NB * ND];
__device__ float g_res1[(size_t)NB * ND];
__device__ float g_norm[(size_t)NB * ND];
__device__ float g_mid[(size_t)NB * 2 * ND];
__device__ float g_bnsum[NA * ND];
__device__ float g_bnsq[NA * ND];
__device__ int   g_cnt[NA];

// ---------------- helpers ----------------
__device__ __forceinline__ float geluf(float x) {
    return 0.5f * x * (1.0f + erff(x * 0.70710678118654752f));
}

__device__ __forceinline__ ull dup2(float x) {
    ull r;
    asm("mov.b64 %0, {%1, %1};" : "=l"(r) : "f"(x));
    return r;
}
__device__ __forceinline__ ull pack2(float lo, float hi) {
    ull r;
    asm("mov.b64 %0, {%1, %2};" : "=l"(r) : "f"(lo), "f"(hi));
    return r;
}
__device__ __forceinline__ void ffma2(ull &d, ull a, ull b) {
    asm("fma.rn.f32x2 %0, %1, %2, %0;" : "+l"(d) : "l"(a), "l"(b));
}
__device__ __forceinline__ float lo2(ull v) { return __uint_as_float((unsigned)(v & 0xFFFFFFFFu)); }
__device__ __forceinline__ float hi2(ull v) { return __uint_as_float((unsigned)(v >> 32)); }

// two-value block reduction (sum); result broadcast to all threads
__device__ __forceinline__ void blockReduce2(float &a, float &b) {
    __shared__ float sa[32], sb[32];
#pragma unroll
    for (int o = 16; o; o >>= 1) {
        a += __shfl_xor_sync(0xFFFFFFFFu, a, o);
        b += __shfl_xor_sync(0xFFFFFFFFu, b, o);
    }
    const int lane = threadIdx.x & 31, w = threadIdx.x >> 5;
    const int nw = blockDim.x >> 5;
    if (nw > 1) {
        if (lane == 0) { sa[w] = a; sb[w] = b; }
        __syncthreads();
        a = (lane < nw) ? sa[lane] : 0.0f;
        b = (lane < nw) ? sb[lane] : 0.0f;
#pragma unroll
        for (int o = 16; o; o >>= 1) {
            a += __shfl_xor_sync(0xFFFFFFFFu, a, o);
            b += __shfl_xor_sync(0xFFFFFFFFu, b, o);
        }
        __syncthreads();
    }
}

// ---------------- SGEMM: C[M,N] = A[M,K] @ B[K,N] (+C) + bias, epilogue -----
// EPI: 0 = bias, 1 = bias+gelu, 2 = bias+sigmoid gate combine f1/f2
// Requires M%128==0, N%128==0, K%16==0.
template <int EPI, bool ACC>
__global__ __launch_bounds__(256) void sgemm(
    const float *__restrict__ Amat, const float *__restrict__ Bmat,
    const float *__restrict__ bias, float *__restrict__ C,
    int M, int N, int K,
    const float *__restrict__ e1, const float *__restrict__ e2)
{
    __shared__ float As[16][128];
    __shared__ float Bs[16][128];
    const int tid = threadIdx.x;
    const int tx = tid & 15, ty = tid >> 4;
    const size_t rowBase = (size_t)blockIdx.y * 128;
    const size_t colBase = (size_t)blockIdx.x * 128;

    ull acc[8][4];
#pragma unroll
    for (int i = 0; i < 8; i++)
#pragma unroll
        for (int j = 0; j < 4; j++) acc[i][j] = 0ull;

    for (int kt = 0; kt < K; kt += 16) {
#pragma unroll
        for (int s = 0; s < 2; s++) {
            int f4 = s * 256 + tid;
            int ar = f4 >> 2, ac = (f4 & 3) << 2;
            const float4 v = *(const float4 *)(Amat + (rowBase + ar) * (size_t)K + kt + ac);
            As[ac + 0][ar] = v.x; As[ac + 1][ar] = v.y;
            As[ac + 2][ar] = v.z; As[ac + 3][ar] = v.w;
        }
#pragma unroll
        for (int s = 0; s < 2; s++) {
            int f4 = s * 256 + tid;
            int br = f4 >> 5, bc = (f4 & 31) << 2;
            *(float4 *)(&Bs[br][bc]) =
                *(const float4 *)(Bmat + (size_t)(kt + br) * N + colBase + bc);
        }
        __syncthreads();
#pragma unroll
        for (int k = 0; k < 16; k++) {
            float a[8];
            *(float4 *)(a)     = *(const float4 *)&As[k][ty * 4];
            *(float4 *)(a + 4) = *(const float4 *)&As[k][64 + ty * 4];
            float4 b0 = *(const float4 *)&Bs[k][tx * 4];
            float4 b1 = *(const float4 *)&Bs[k][64 + tx * 4];
            ull bp[4];
            bp[0] = pack2(b0.x, b0.y); bp[1] = pack2(b0.z, b0.w);
            bp[2] = pack2(b1.x, b1.y); bp[3] = pack2(b1.z, b1.w);
#pragma unroll
            for (int i = 0; i < 8; i++) {
                ull ad = dup2(a[i]);
#pragma unroll
                for (int j = 0; j < 4; j++) ffma2(acc[i][j], ad, bp[j]);
            }
        }
        __syncthreads();
    }

    // epilogue
#pragma unroll
    for (int i = 0; i < 8; i++) {
        size_t r = rowBase + ((i < 4) ? (ty * 4 + i) : (64 + ty * 4 + i - 4));
#pragma unroll
        for (int jh = 0; jh < 2; jh++) {
            size_t c0 = colBase + jh * 64 + tx * 4;
            float v[4];
            v[0] = lo2(acc[i][jh * 2]);     v[1] = hi2(acc[i][jh * 2]);
            v[2] = lo2(acc[i][jh * 2 + 1]); v[3] = hi2(acc[i][jh * 2 + 1]);
            if (ACC) {
                float4 old = *(const float4 *)(C + r * (size_t)N + c0);
                v[0] += old.x; v[1] += old.y; v[2] += old.z; v[3] += old.w;
            }
            if (bias) {
                float4 bv = *(const float4 *)(bias + c0);
                v[0] += bv.x; v[1] += bv.y; v[2] += bv.z; v[3] += bv.w;
            }
            float4 out;
            float *o = (float *)&out;
#pragma unroll
            for (int j = 0; j < 4; j++) {
                float x = v[j];
                if (EPI == 1) x = geluf(x);
                if (EPI == 2) {
                    float s = 1.0f / (1.0f + expf(-x));
                    size_t idx = r * (size_t)N + c0 + j;
                    x = s * e1[idx] + (1.0f - s) * e2[idx];
                }
                o[j] = x;
            }
            *(float4 *)(C + r * (size_t)N + c0) = out;
        }
    }
}

// ---------------- LN (+ optional exact GELU), in place, rows of length N ----
// launch: grid = NB, block = N/4 (<=256)
template <bool DOGELU>
__global__ void ln_act(float *__restrict__ x, const float *__restrict__ g,
                       const float *__restrict__ b, int N)
{
    const size_t row = blockIdx.x;
    float4 *xr = (float4 *)(x + row * (size_t)N);
    const int t = threadIdx.x;
    float4 v = xr[t];
    float s = v.x + v.y + v.z + v.w;
    float sq = v.x * v.x + v.y * v.y + v.z * v.z + v.w * v.w;
    blockReduce2(s, sq);
    const float invN = 1.0f / (float)N;
    float mu = s * invN;
    float var = sq * invN - mu * mu;
    float rs = rsqrtf(var + LNEPS);
    float4 gv = ((const float4 *)g)[t];
    float4 bv = ((const float4 *)b)[t];
    v.x = (v.x - mu) * rs * gv.x + bv.x;
    v.y = (v.y - mu) * rs * gv.y + bv.y;
    v.z = (v.z - mu) * rs * gv.z + bv.z;
    v.w = (v.w - mu) * rs * gv.w + bv.w;
    if (DOGELU) {
        v.x = geluf(v.x); v.y = geluf(v.y); v.z = geluf(v.z); v.w = geluf(v.w);
    }
    xr[t] = v;
}

// ---------------- fused attention + 2x LN: writes res1 ----------------------
// block = 256 threads, one row per block; D = 2048 -> 2 float4 per thread
__global__ __launch_bounds__(256) void attn_fused(
    const float *__restrict__ q, const float *__restrict__ k1,
    const float *__restrict__ k2, const float *__restrict__ v1,
    const float *__restrict__ v2, const float *__restrict__ gf,
    const float *__restrict__ f1,
    const float *__restrict__ alng, const float *__restrict__ alnb,
    const float *__restrict__ ln1g, const float *__restrict__ ln1b,
    float *__restrict__ out)
{
    const size_t row = blockIdx.x;
    const size_t base4 = row * (ND / 4);
    const int t = threadIdx.x;

    float s1 = 0.0f, s2 = 0.0f;
#pragma unroll
    for (int p = 0; p < 2; p++) {
        int idx = t + p * 256;
        float4 qv = ((const float4 *)q)[base4 + idx];
        float4 a = ((const float4 *)k1)[base4 + idx];
        float4 b = ((const float4 *)k2)[base4 + idx];
        s1 += qv.x * a.x + qv.y * a.y + qv.z * a.z + qv.w * a.w;
        s2 += qv.x * b.x + qv.y * b.y + qv.z * b.z + qv.w * b.w;
    }
    blockReduce2(s1, s2);
    s1 *= (1.0f / SQRT_D);
    s2 *= (1.0f / SQRT_D);
    float m = fmaxf(s1, s2);
    float e1v = expf(s1 - m), e2v = expf(s2 - m);
    float w1 = e1v / (e1v + e2v), w2 = 1.0f - w1;

    float4 xv[2];
    float s = 0.0f, sq = 0.0f;
#pragma unroll
    for (int p = 0; p < 2; p++) {
        int idx = t + p * 256;
        float4 gv = ((const float4 *)gf)[base4 + idx];
        float4 a = ((const float4 *)v1)[base4 + idx];
        float4 b = ((const float4 *)v2)[base4 + idx];
        float4 x;
        x.x = gv.x + w1 * a.x + w2 * b.x;
        x.y = gv.y + w1 * a.y + w2 * b.y;
        x.z = gv.z + w1 * a.z + w2 * b.z;
        x.w = gv.w + w1 * a.w + w2 * b.w;
        xv[p] = x;
        s += x.x + x.y + x.z + x.w;
        sq += x.x * x.x + x.y * x.y + x.z * x.z + x.w * x.w;
    }
    blockReduce2(s, sq);
    const float invD = 1.0f / (float)ND;
    float mu = s * invD;
    float var = sq * invD - mu * mu;
    float rs = rsqrtf(var + LNEPS);

    float4 yv[2];
    float s3 = 0.0f, sq3 = 0.0f;
#pragma unroll
    for (int p = 0; p < 2; p++) {
        int idx = t + p * 256;
        float4 gv = ((const float4 *)alng)[idx];
        float4 bv = ((const float4 *)alnb)[idx];
        float4 fv = ((const float4 *)f1)[base4 + idx];
        float4 x = xv[p], y;
        y.x = (x.x - mu) * rs * gv.x + bv.x + fv.x;
        y.y = (x.y - mu) * rs * gv.y + bv.y + fv.y;
        y.z = (x.z - mu) * rs * gv.z + bv.z + fv.z;
        y.w = (x.w - mu) * rs * gv.w + bv.w + fv.w;
        yv[p] = y;
        s3 += y.x + y.y + y.z + y.w;
        sq3 += y.x * y.x + y.y * y.y + y.z * y.z + y.w * y.w;
    }
    blockReduce2(s3, sq3);
    float mu2 = s3 * invD;
    float var2 = sq3 * invD - mu2 * mu2;
    float rs2 = rsqrtf(var2 + LNEPS);
#pragma unroll
    for (int p = 0; p < 2; p++) {
        int idx = t + p * 256;
        float4 gv = ((const float4 *)ln1g)[idx];
        float4 bv = ((const float4 *)ln1b)[idx];
        float4 y = yv[p], o;
        o.x = (y.x - mu2) * rs2 * gv.x + bv.x;
        o.y = (y.y - mu2) * rs2 * gv.y + bv.y;
        o.z = (y.z - mu2) * rs2 * gv.z + bv.z;
        o.w = (y.w - mu2) * rs2 * gv.w + bv.w;
        ((float4 *)out)[base4 + idx] = o;
    }
}

// ---------------- aspect BN ----------------
__global__ void bn_count(const int *__restrict__ ids) {
    __shared__ int c[NA];
    if (threadIdx.x < NA) c[threadIdx.x] = 0;
    __syncthreads();
    for (int i = threadIdx.x; i < NB; i += blockDim.x) atomicAdd(&c[ids[i]], 1);
    __syncthreads();
    if (threadIdx.x < NA) g_cnt[threadIdx.x] = c[threadIdx.x];
}

// grid = ND/32 blocks, 256 threads: 32 columns x 8 row-stripes per block
__global__ __launch_bounds__(256) void bn_stats(const float *__restrict__ x,
                                                const int *__restrict__ ids)
{
    __shared__ float ssum[NA][32], ssq[NA][32];
    const int lane = threadIdx.x & 31;
    const int stripe = threadIdx.x >> 5;
    const int c = blockIdx.x * 32 + lane;
    if (stripe == 0) {
#pragma unroll
        for (int a = 0; a < NA; a++) { ssum[a][lane] = 0.0f; ssq[a][lane] = 0.0f; }
    }
    __syncthreads();
    float s0 = 0, s1 = 0, s2 = 0, q0 = 0, q1 = 0, q2 = 0;
#pragma unroll 4
    for (int r = stripe; r < NB; r += 8) {
        int a = ids[r];
        float v = x[(size_t)r * ND + c];
        float vv = v * v;
        if (a == 0) { s0 += v; q0 += vv; }
        else if (a == 1) { s1 += v; q1 += vv; }
        else { s2 += v; q2 += vv; }
    }
    atomicAdd(&ssum[0][lane], s0); atomicAdd(&ssq[0][lane], q0);
    atomicAdd(&ssum[1][lane], s1); atomicAdd(&ssq[1][lane], q1);
    atomicAdd(&ssum[2][lane], s2); atomicAdd(&ssq[2][lane], q2);
    __syncthreads();
    if (stripe < NA) {
        g_bnsum[stripe * ND + c] = ssum[stripe][lane];
        g_bnsq[stripe * ND + c] = ssq[stripe][lane];
    }
}

// elementwise apply; one float4 per thread
__global__ void bn_apply(const float *__restrict__ x, const int *__restrict__ ids,
                         const float *__restrict__ bng, const float *__restrict__ bnb,
                         float *__restrict__ out)
{
    const int i = blockIdx.x * blockDim.x + threadIdx.x;  // float4 index
    const int row = i >> 9;        // ND/4 = 512
    const int c4 = i & 511;
    const int a = ids[row];
    const int cnt = g_cnt[a];
    float4 v = ((const float4 *)x)[i];
    if (cnt > 1) {
        const float fc = (float)cnt;
        const int cb4 = (a * ND) / 4 + c4;
        float4 sm = ((const float4 *)g_bnsum)[cb4];
        float4 sc = ((const float4 *)g_bnsq)[cb4];
        float4 gv = ((const float4 *)bng)[cb4];
        float4 bv = ((const float4 *)bnb)[cb4];
        float m, vr;
        m = sm.x / fc; vr = sc.x / fc - m * m; v.x = (v.x - m) * rsqrtf(vr + LNEPS) * gv.x + bv.x;
        m = sm.y / fc; vr = sc.y / fc - m * m; v.y = (v.y - m) * rsqrtf(vr + LNEPS) * gv.y + bv.y;
        m = sm.z / fc; vr = sc.z / fc - m * m; v.z = (v.z - m) * rsqrtf(vr + LNEPS) * gv.z + bv.z;
        m = sm.w / fc; vr = sc.w / fc - m * m; v.w = (v.w - m) * rsqrtf(vr + LNEPS) * gv.w + bv.w;
    }
    ((float4 *)out)[i] = v;
}

// ---------------- final LN(a + b) -> out ----------------
__global__ __launch_bounds__(256) void ln_residual(
    const float *__restrict__ x, const float *__restrict__ res,
    const float *__restrict__ g, const float *__restrict__ b,
    float *__restrict__ out)
{
    const size_t base4 = (size_t)blockIdx.x * (ND / 4);
    const int t = threadIdx.x;
    float4 v[2];
    float s = 0.0f, sq = 0.0f;
#pragma unroll
    for (int p = 0; p < 2; p++) {
        int idx = t + p * 256;
        float4 a = ((const float4 *)x)[base4 + idx];
        float4 r = ((const float4 *)res)[base4 + idx];
        a.x += r.x; a.y += r.y; a.z += r.z; a.w += r.w;
        v[p] = a;
        s += a.x + a.y + a.z + a.w;
        sq += a.x * a.x + a.y * a.y + a.z * a.z + a.w * a.w;
    }
    blockReduce2(s, sq);
    const float invD = 1.0f / (float)ND;
    float mu = s * invD;
    float var = sq * invD - mu * mu;
    float rs = rsqrtf(var + LNEPS);
#pragma unroll
    for (int p = 0; p < 2; p++) {
        int idx = t + p * 256;
        float4 gv = ((const float4 *)g)[idx];
        float4 bv = ((const float4 *)b)[idx];
        float4 a = v[p], o;
        o.x = (a.x - mu) * rs * gv.x + bv.x;
        o.y = (a.y - mu) * rs * gv.y + bv.y;
        o.z = (a.z - mu) * rs * gv.z + bv.z;
        o.w = (a.w - mu) * rs * gv.w + bv.w;
        ((float4 *)out)[base4 + idx] = o;
    }
}

// ---------------- launch ----------------
extern "C" void kernel_launch(void *const *d_in, const int *in_sizes, int n_in,
                              void *d_out, int out_size)
{
    const float *f1 = (const float *)d_in[0];
    const float *f2 = (const float *)d_in[1];
    const int *ids = (const int *)d_in[2];
    const float *gW1 = (const float *)d_in[3], *gb1 = (const float *)d_in[4];
    const float *gl1g = (const float *)d_in[5], *gl1b = (const float *)d_in[6];
    const float *gW2 = (const float *)d_in[7], *gb2 = (const float *)d_in[8];
    const float *gl2g = (const float *)d_in[9], *gl2b = (const float *)d_in[10];
    const float *gW3 = (const float *)d_in[11], *gb3 = (const float *)d_in[12];
    const float *qW = (const float *)d_in[13], *qb = (const float *)d_in[14];
    const float *kW = (const float *)d_in[15], *kb = (const float *)d_in[16];
    const float *vW = (const float *)d_in[17], *vb = (const float *)d_in[18];
    const float *alng = (const float *)d_in[19], *alnb = (const float *)d_in[20];
    const float *bng = (const float *)d_in[21], *bnb = (const float *)d_in[22];
    const float *ln1g = (const float *)d_in[23], *ln1b = (const float *)d_in[24];
    const float *fW1 = (const float *)d_in[25], *fb1 = (const float *)d_in[26];
    const float *fW2 = (const float *)d_in[27], *fb2 = (const float *)d_in[28];
    const float *ln2g = (const float *)d_in[29], *ln2b = (const float *)d_in[30];
    float *out = (float *)d_out;

    float *h1, *h2, *gf, *q, *k1, *k2, *v1, *v2, *res1, *nrm, *mid;
    cudaGetSymbolAddress((void **)&h1, g_h1);
    cudaGetSymbolAddress((void **)&h2, g_h2);
    cudaGetSymbolAddress((void **)&gf, g_gf);
    cudaGetSymbolAddress((void **)&q, g_q);
    cudaGetSymbolAddress((void **)&k1, g_k1);
    cudaGetSymbolAddress((void **)&k2, g_k2);
    cudaGetSymbolAddress((void **)&v1, g_v1);
    cudaGetSymbolAddress((void **)&v2, g_v2);
    cudaGetSymbolAddress((void **)&res1, g_res1);
    cudaGetSymbolAddress((void **)&nrm, g_norm);
    cudaGetSymbolAddress((void **)&mid, g_mid);

    const dim3 gL1(NH / 128, NB / 128);        // 4 x 64
    const dim3 gL2((NH / 2) / 128, NB / 128);  // 2 x 64
    const dim3 gD(ND / 128, NB / 128);         // 16 x 64
    const dim3 g2D((2 * ND) / 128, NB / 128);  // 32 x 64

    // gate MLP layer 1: h1 = concat(f1,f2) @ gW1 + gb1 (split as two GEMMs)
    sgemm<0, false><<<gL1, 256>>>(f1, gW1, nullptr, h1, NB, NH, ND, nullptr, nullptr);
    sgemm<0, true><<<gL1, 256>>>(f2, gW1 + (size_t)ND * NH, gb1, h1, NB, NH, ND, nullptr, nullptr);
    ln_act<true><<<NB, NH / 4>>>(h1, gl1g, gl1b, NH);
    // layer 2
    sgemm<0, false><<<gL2, 256>>>(h1, gW2, gb2, h2, NB, NH / 2, NH, nullptr, nullptr);
    ln_act<true><<<NB, (NH / 2) / 4>>>(h2, gl2g, gl2b, NH / 2);
    // layer 3 + sigmoid gate combine -> gf
    sgemm<2, false><<<gD, 256>>>(h2, gW3, gb3, gf, NB, ND, NH / 2, f1, f2);
    // attention projections
    sgemm<0, false><<<gD, 256>>>(gf, qW, qb, q, NB, ND, ND, nullptr, nullptr);
    sgemm<0, false><<<gD, 256>>>(f1, kW, kb, k1, NB, ND, ND, nullptr, nullptr);
    sgemm<0, false><<<gD, 256>>>(f2, kW, kb, k2, NB, ND, ND, nullptr, nullptr);
    sgemm<0, false><<<gD, 256>>>(f1, vW, vb, v1, NB, ND, ND, nullptr, nullptr);
    sgemm<0, false><<<gD, 256>>>(f2, vW, vb, v2, NB, ND, ND, nullptr, nullptr);
    // fused attention + LN(gf+attn) + LN(gated+f1) -> res1
    attn_fused<<<NB, 256>>>(q, k1, k2, v1, v2, gf, f1, alng, alnb, ln1g, ln1b, res1);
    // aspect BN
    bn_count<<<1, 256>>>(ids);
    bn_stats<<<ND / 32, 256>>>(res1, ids);
    bn_apply<<<(NB * ND / 4) / 256, 256>>>(res1, ids, bng, bnb, nrm);
    // FFN
    sgemm<1, false><<<g2D, 256>>>(nrm, fW1, fb1, mid, NB, 2 * ND, ND, nullptr, nullptr);
    sgemm<0, false><<<gD, 256>>>(mid, fW2, fb2, q, NB, ND, 2 * ND, nullptr, nullptr);
    // final residual LN -> out
    ln_residual<<<NB, 256>>>(q, nrm, ln2g, ln2b, out);
}

// round 4
// speedup vs baseline: 4.2882x; 4.2882x over previous
#include <cuda_runtime.h>
#include <math.h>
#include <stdint.h>

#define NB 8192
#define ND 2048
#define NH 512
#define NA 3
#define LNEPS 1e-5f
#define SQRT_D 45.25483399593904f

#if defined(__CUDA_ARCH__) && (__CUDA_ARCH__ == 1030) && defined(__CUDA_ARCH_FEAT_SM103_ALL)
#define USE_TC5 1
#else
#define USE_TC5 0
#endif

typedef unsigned long long ull;

// ---------------- scratch (device globals; no allocation allowed) ----------
__device__ float g_h1[(size_t)NB * NH];
__device__ float g_h2[(size_t)NB * (NH / 2)];
__device__ float g_gf[(size_t)NB * ND];
__device__ float g_q[(size_t)NB * ND];
__device__ float g_k1[(size_t)NB * ND];
__device__ float g_k2[(size_t)NB * ND];
__device__ float g_v1[(size_t)NB * ND];
__device__ float g_v2[(size_t)NB * ND];
__device__ float g_res1[(size_t)NB * ND];
__device__ float g_norm[(size_t)NB * ND];
__device__ float g_mid[(size_t)NB * 2 * ND];
__device__ float g_bnsum[NA * ND];
__device__ float g_bnsq[NA * ND];
__device__ int   g_cnt[NA];
__device__ float g_wt[32111424];

#define OF_GW1T 0
#define OF_GW2T (OF_GW1T + 4096 * 512)
#define OF_GW3T (OF_GW2T + 512 * 256)
#define OF_QWT  (OF_GW3T + 256 * 2048)
#define OF_KWT  (OF_QWT + 2048 * 2048)
#define OF_VWT  (OF_KWT + 2048 * 2048)
#define OF_FW1T (OF_VWT + 2048 * 2048)
#define OF_FW2T (OF_FW1T + 2048 * 4096)

// ---------------- helpers ----------------
__device__ __forceinline__ float geluf(float x) {
    return 0.5f * x * (1.0f + erff(x * 0.70710678118654752f));
}
__device__ __forceinline__ uint32_t smem_u32(const void *p) {
    uint32_t a;
    asm("{ .reg .u64 t; cvta.to.shared.u64 t, %1; cvt.u32.u64 %0, t; }" : "=r"(a) : "l"(p));
    return a;
}
__device__ __forceinline__ uint32_t swz128(uint32_t off) {
    return off ^ ((off >> 3) & 0x70u);
}
__device__ __forceinline__ void cp16(uint32_t s, const void *g) {
    asm volatile("cp.async.cg.shared.global [%0], [%1], 16;" :: "r"(s), "l"(g));
}
__device__ __forceinline__ void cp_commit() { asm volatile("cp.async.commit_group;" ::: "memory"); }
template <int N> __device__ __forceinline__ void cp_wait() {
    asm volatile("cp.async.wait_group %0;" :: "n"(N) : "memory");
}
__device__ __forceinline__ uint32_t f2tf32(float f) {
    uint32_t r;
    asm("cvt.rna.tf32.f32 %0, %1;" : "=r"(r) : "f"(f));
    return r;
}
__device__ __forceinline__ void hmma_tf32(float *c, const uint32_t *a, const uint32_t *b) {
    asm volatile(
        "mma.sync.aligned.m16n8k8.row.col.f32.tf32.tf32.f32 "
        "{%0,%1,%2,%3}, {%4,%5,%6,%7}, {%8,%9}, {%0,%1,%2,%3};"
        : "+f"(c[0]), "+f"(c[1]), "+f"(c[2]), "+f"(c[3])
        : "r"(a[0]), "r"(a[1]), "r"(a[2]), "r"(a[3]), "r"(b[0]), "r"(b[1]));
}
#if USE_TC5
__device__ __forceinline__ uint32_t elect_one() {
    uint32_t p;
    asm volatile("{ .reg .pred p; elect.sync _|p, 0xFFFFFFFF; selp.b32 %0, 1, 0, p; }" : "=r"(p));
    return p;
}
__device__ __forceinline__ void mbar_init(uint32_t a, uint32_t cnt) {
    asm volatile("mbarrier.init.shared.b64 [%0], %1;" :: "r"(a), "r"(cnt) : "memory");
}
__device__ __forceinline__ void mbar_wait(uint32_t a, uint32_t ph) {
    asm volatile(
        "{ .reg .pred P;\n"
        "L_%=: mbarrier.try_wait.parity.acquire.cta.shared::cta.b64 P, [%0], %1, 0x989680;\n"
        "@P bra D_%=;\n bra L_%=;\n D_%=: }"
        :: "r"(a), "r"(ph) : "memory");
}
__device__ __forceinline__ void mbar_inval(uint32_t a) {
    asm volatile("mbarrier.inval.shared.b64 [%0];" :: "r"(a) : "memory");
}
__device__ __forceinline__ uint64_t make_desc(uint32_t addr) {
    return (2ULL << 61) | (1ULL << 46) | (64ULL << 32) | (1ULL << 16) |
           ((uint64_t)(addr >> 4) & 0x3FFFULL);
}
__device__ __forceinline__ void mma_tf32(uint32_t d, uint64_t ad, uint64_t bd,
                                         uint32_t idesc, uint32_t en) {
    asm volatile(
        "{ .reg .pred p;\n setp.ne.u32 p, %4, 0;\n"
        "tcgen05.mma.cta_group::1.kind::tf32 [%0], %1, %2, %3, {%5, %5, %5, %5}, p;\n }"
        :: "r"(d), "l"(ad), "l"(bd), "r"(idesc), "r"(en), "r"(0u) : "memory");
}
__device__ __forceinline__ void tc_commit(uint32_t mb) {
    asm volatile(
        "tcgen05.commit.cta_group::1.mbarrier::arrive::one.shared::cluster.b64 [%0];"
        :: "r"(mb) : "memory");
}
#endif

// two-value block reduction (sum); result broadcast to all threads
__device__ __forceinline__ void blockReduce2(float &a, float &b) {
    __shared__ float sa[32], sb[32];
#pragma unroll
    for (int o = 16; o; o >>= 1) {
        a += __shfl_xor_sync(0xFFFFFFFFu, a, o);
        b += __shfl_xor_sync(0xFFFFFFFFu, b, o);
    }
    const int lane = threadIdx.x & 31, w = threadIdx.x >> 5;
    const int nw = blockDim.x >> 5;
    if (nw > 1) {
        if (lane == 0) { sa[w] = a; sb[w] = b; }
        __syncthreads();
        a = (lane < nw) ? sa[lane] : 0.0f;
        b = (lane < nw) ? sb[lane] : 0.0f;
#pragma unroll
        for (int o = 16; o; o >>= 1) {
            a += __shfl_xor_sync(0xFFFFFFFFu, a, o);
            b += __shfl_xor_sync(0xFFFFFFFFu, b, o);
        }
        __syncthreads();
    }
}

// ---------------- weight transpose: in[K,N] -> out[N,K] ----------------
__global__ void transp(const float *__restrict__ in, float *__restrict__ out,
                       int K, int N) {
    __shared__ float t[32][33];
    const int n0 = blockIdx.x * 32, k0 = blockIdx.y * 32;
#pragma unroll
    for (int i = threadIdx.y; i < 32; i += 8)
        t[i][threadIdx.x] = in[(size_t)(k0 + i) * N + n0 + threadIdx.x];
    __syncthreads();
#pragma unroll
    for (int i = threadIdx.y; i < 32; i += 8)
        out[(size_t)(n0 + i) * K + k0 + threadIdx.x] = t[threadIdx.x][i];
}

// ---------------- tf32 GEMM: C = concat_K(A1,A2) @ WT^T + bias -------------
// WT is [N, Ktot] K-major. CTA tile 128x128, K chunk 32, double buffered.
// EPI: 0 = bias, 1 = bias+gelu, 2 = bias+sigmoid gate combine e1/e2
#define GT_M 128
#define GT_N 128
#define GK 32
#define SMA_SZ (GT_M * GK * 4)          // 16384
#define SMB_SZ (GT_N * GK * 4)          // 16384
#define SMBUF  (SMA_SZ + SMB_SZ)        // 32768
#define SM_TOTAL (2048 + 2 * SMBUF)     // 67584
#define TMEM_COLS 128
#define IDESC_TF32 ((1u << 4) | (2u << 7) | (2u << 10) | ((GT_N / 8) << 17) | ((GT_M / 16) << 24))

template <int EPI>
__global__ __launch_bounds__(256) void tgemm(
    const float *__restrict__ A1, const float *__restrict__ A2,
    const float *__restrict__ WT, const float *__restrict__ bias,
    float *__restrict__ C, int M, int N, int K1, int K2,
    const float *__restrict__ e1, const float *__restrict__ e2)
{
    extern __shared__ char smem[];
    const uint32_t sb = smem_u32(smem);
    const uint32_t tile0 = (sb + 1024 + 1023) & ~1023u;  // 1024-aligned tile base
    char *smem_tile0 = smem + (tile0 - sb);
    const int tid = threadIdx.x;
    const int wid = tid >> 5, lane = tid & 31;
    const size_t rowBase = (size_t)blockIdx.y * GT_M;
    const size_t colBase = (size_t)blockIdx.x * GT_N;
    const int K = K1 + K2;
    const int niter = K / GK;

    // per-thread load chunks (16B, 8 per 128B row); A:128 rows, B:128 rows
    uint32_t aoff[4], boff[4];
    const float *pA1[4], *pA2[4], *pB[4];
#pragma unroll
    for (int i = 0; i < 4; i++) {
        int c = tid + i * 256, r = c >> 3, k16 = c & 7;
        aoff[i] = swz128((uint32_t)(r * 128 + k16 * 16));
        pA1[i] = A1 + (rowBase + r) * (size_t)K1 + k16 * 4;
        pA2[i] = A2 + (rowBase + r) * (size_t)K2 + k16 * 4 - K1;
        boff[i] = SMA_SZ + aoff[i];
        pB[i] = WT + (colBase + r) * (size_t)K + k16 * 4;
    }

#if USE_TC5
    if (wid == 0)
        asm volatile("tcgen05.alloc.cta_group::1.sync.aligned.shared::cta.b32 [%0], %1;"
                     :: "r"(sb), "r"(TMEM_COLS) : "memory");
    if (tid == 0) { mbar_init(sb + 16, 1); mbar_init(sb + 24, 1); }
    __syncthreads();
    uint32_t tmem;
    asm("ld.shared.b32 %0, [%1];" : "=r"(tmem) : "r"(sb));
    if (wid == 0)
        asm volatile("tcgen05.relinquish_alloc_permit.cta_group::1.sync.aligned;");

    // prologue into buffer 0
#pragma unroll
    for (int i = 0; i < 4; i++) cp16(tile0 + aoff[i], pA1[i]);
#pragma unroll
    for (int i = 0; i < 4; i++) cp16(tile0 + boff[i], pB[i]);
    cp_commit();

    uint32_t ph0 = 0, ph1 = 0;
    for (int it = 0; it < niter; ++it) {
        const int b = it & 1;
        if (it + 1 < niter) {
            const int nb = b ^ 1;
            if (it >= 1) {
                if (nb == 0) { mbar_wait(sb + 16, ph0); ph0 ^= 1; }
                else         { mbar_wait(sb + 24, ph1); ph1 ^= 1; }
            }
            const int kg = (it + 1) * GK;
            const uint32_t tb = tile0 + nb * SMBUF;
            const bool s1 = kg < K1;
#pragma unroll
            for (int i = 0; i < 4; i++)
                cp16(tb + aoff[i], (s1 ? pA1[i] : pA2[i]) + kg);
#pragma unroll
            for (int i = 0; i < 4; i++) cp16(tb + boff[i], pB[i] + kg);
            cp_commit();
            cp_wait<1>();
        } else {
            cp_wait<0>();
        }
        asm volatile("fence.proxy.async.shared::cta;" ::: "memory");
        __syncthreads();
        if (wid == 0 && elect_one()) {
            const uint32_t tb = tile0 + b * SMBUF;
            uint64_t ad = make_desc(tb), bd = make_desc(tb + SMA_SZ);
#pragma unroll
            for (int s = 0; s < 4; s++)
                mma_tf32(tmem, ad + 2 * s, bd + 2 * s, IDESC_TF32,
                         (it > 0 || s > 0) ? 1u : 0u);
            tc_commit(sb + 16 + 8 * b);
        }
    }
    {
        const int bl = (niter - 1) & 1;
        if (bl == 0) mbar_wait(sb + 16, ph0);
        else         mbar_wait(sb + 24, ph1);
    }
    asm volatile("tcgen05.fence::after_thread_sync;" ::: "memory");

    if (wid < 4) {
        const size_t m = rowBase + wid * 32 + lane;
        const size_t crow = m * (size_t)N;
#pragma unroll 1
        for (int nb = 0; nb < 4; ++nb) {
            uint32_t r[32];
            asm volatile(
                "tcgen05.ld.sync.aligned.32x32b.x32.b32 "
                "{%0,%1,%2,%3,%4,%5,%6,%7,%8,%9,%10,%11,%12,%13,%14,%15,"
                "%16,%17,%18,%19,%20,%21,%22,%23,%24,%25,%26,%27,%28,%29,%30,%31}, [%32];"
                : "=r"(r[0]), "=r"(r[1]), "=r"(r[2]), "=r"(r[3]), "=r"(r[4]),
                  "=r"(r[5]), "=r"(r[6]), "=r"(r[7]), "=r"(r[8]), "=r"(r[9]),
                  "=r"(r[10]), "=r"(r[11]), "=r"(r[12]), "=r"(r[13]), "=r"(r[14]),
                  "=r"(r[15]), "=r"(r[16]), "=r"(r[17]), "=r"(r[18]), "=r"(r[19]),
                  "=r"(r[20]), "=r"(r[21]), "=r"(r[22]), "=r"(r[23]), "=r"(r[24]),
                  "=r"(r[25]), "=r"(r[26]), "=r"(r[27]), "=r"(r[28]), "=r"(r[29]),
                  "=r"(r[30]), "=r"(r[31])
                : "r"(tmem + nb * 32));
            asm volatile("tcgen05.wait::ld.sync.aligned;" ::: "memory");
            const size_t c0 = colBase + nb * 32;
#pragma unroll
            for (int j4 = 0; j4 < 8; ++j4) {
                float4 bv = *(const float4 *)(bias + c0 + j4 * 4);
                float v[4];
                v[0] = __uint_as_float(r[j4 * 4 + 0]) + bv.x;
                v[1] = __uint_as_float(r[j4 * 4 + 1]) + bv.y;
                v[2] = __uint_as_float(r[j4 * 4 + 2]) + bv.z;
                v[3] = __uint_as_float(r[j4 * 4 + 3]) + bv.w;
                float4 o;
                float *op = (float *)&o;
                if (EPI == 2) {
                    float4 a = *(const float4 *)(e1 + crow + c0 + j4 * 4);
                    float4 b2 = *(const float4 *)(e2 + crow + c0 + j4 * 4);
                    const float *ap = (const float *)&a, *bp = (const float *)&b2;
#pragma unroll
                    for (int j = 0; j < 4; j++) {
                        float s = 1.0f / (1.0f + expf(-v[j]));
                        op[j] = s * ap[j] + (1.0f - s) * bp[j];
                    }
                } else {
#pragma unroll
                    for (int j = 0; j < 4; j++)
                        op[j] = (EPI == 1) ? geluf(v[j]) : v[j];
                }
                *(float4 *)(C + crow + c0 + j4 * 4) = o;
            }
        }
    }
    __syncthreads();
    if (tid == 0) { mbar_inval(sb + 16); mbar_inval(sb + 24); }
    __syncthreads();
    if (wid == 0)
        asm volatile("tcgen05.dealloc.cta_group::1.sync.aligned.b32 %0, %1;"
                     :: "r"(tmem), "r"(TMEM_COLS));

#else  // ---------------- mma.sync tf32 fallback ----------------
    // warps 4(M) x 2(N): warp tile 32 x 64 = 2 x 8 mma tiles of m16n8k8
    const int warpM = (wid >> 1) * 32, warpN = (wid & 1) * 64;
    const int r0 = lane >> 2, kq = lane & 3;
    float acc[2][8][4];
#pragma unroll
    for (int mt = 0; mt < 2; mt++)
#pragma unroll
        for (int nt = 0; nt < 8; nt++)
#pragma unroll
            for (int j = 0; j < 4; j++) acc[mt][nt][j] = 0.0f;

    // prologue into buffer 0
#pragma unroll
    for (int i = 0; i < 4; i++) cp16(tile0 + aoff[i], pA1[i]);
#pragma unroll
    for (int i = 0; i < 4; i++) cp16(tile0 + boff[i], pB[i]);
    cp_commit();

    for (int it = 0; it < niter; ++it) {
        const int b = it & 1;
        if (it + 1 < niter) {
            const int nb = b ^ 1;
            const int kg = (it + 1) * GK;
            const uint32_t tb = tile0 + nb * SMBUF;
            const bool s1 = kg < K1;
#pragma unroll
            for (int i = 0; i < 4; i++)
                cp16(tb + aoff[i], (s1 ? pA1[i] : pA2[i]) + kg);
#pragma unroll
            for (int i = 0; i < 4; i++) cp16(tb + boff[i], pB[i] + kg);
            cp_commit();
            cp_wait<1>();
        } else {
            cp_wait<0>();
        }
        __syncthreads();
        const char *ta = smem_tile0 + b * SMBUF;
        const char *tb2 = ta + SMA_SZ;
#pragma unroll
        for (int k8 = 0; k8 < GK / 8; ++k8) {
            const int kb = k8 * 8;
            uint32_t af[2][4];
#pragma unroll
            for (int mt = 0; mt < 2; mt++) {
                int rb = warpM + mt * 16;
                af[mt][0] = f2tf32(*(const float *)(ta + swz128((rb + r0) * 128 + (kb + kq) * 4)));
                af[mt][1] = f2tf32(*(const float *)(ta + swz128((rb + r0 + 8) * 128 + (kb + kq) * 4)));
                af[mt][2] = f2tf32(*(const float *)(ta + swz128((rb + r0) * 128 + (kb + kq + 4) * 4)));
                af[mt][3] = f2tf32(*(const float *)(ta + swz128((rb + r0 + 8) * 128 + (kb + kq + 4) * 4)));
            }
            uint32_t bf[8][2];
#pragma unroll
            for (int nt = 0; nt < 8; nt++) {
                int n0 = warpN + nt * 8 + r0;
                bf[nt][0] = f2tf32(*(const float *)(tb2 + swz128(n0 * 128 + (kb + kq) * 4)));
                bf[nt][1] = f2tf32(*(const float *)(tb2 + swz128(n0 * 128 + (kb + kq + 4) * 4)));
            }
#pragma unroll
            for (int mt = 0; mt < 2; mt++)
#pragma unroll
                for (int nt = 0; nt < 8; nt++)
                    hmma_tf32(acc[mt][nt], af[mt], bf[nt]);
        }
        __syncthreads();
    }

    // epilogue
#pragma unroll
    for (int mt = 0; mt < 2; mt++) {
#pragma unroll
        for (int half = 0; half < 2; half++) {
            const size_t m = rowBase + warpM + mt * 16 + r0 + half * 8;
            const size_t crow = m * (size_t)N;
#pragma unroll
            for (int nt = 0; nt < 8; nt++) {
                const size_t c0 = colBase + warpN + nt * 8 + 2 * kq;
                float v0 = acc[mt][nt][half * 2 + 0] + bias[c0];
                float v1 = acc[mt][nt][half * 2 + 1] + bias[c0 + 1];
                if (EPI == 1) { v0 = geluf(v0); v1 = geluf(v1); }
                if (EPI == 2) {
                    float s0 = 1.0f / (1.0f + expf(-v0));
                    float s1 = 1.0f / (1.0f + expf(-v1));
                    v0 = s0 * e1[crow + c0] + (1.0f - s0) * e2[crow + c0];
                    v1 = s1 * e1[crow + c0 + 1] + (1.0f - s1) * e2[crow + c0 + 1];
                }
                float2 o = make_float2(v0, v1);
                *(float2 *)(C + crow + c0) = o;
            }
        }
    }
#endif
}

// ---------------- LN (+ optional exact GELU), in place ----------------
template <bool DOGELU>
__global__ void ln_act(float *__restrict__ x, const float *__restrict__ g,
                       const float *__restrict__ b, int N)
{
    const size_t row = blockIdx.x;
    float4 *xr = (float4 *)(x + row * (size_t)N);
    const int t = threadIdx.x;
    float4 v = xr[t];
    float s = v.x + v.y + v.z + v.w;
    float sq = v.x * v.x + v.y * v.y + v.z * v.z + v.w * v.w;
    blockReduce2(s, sq);
    const float invN = 1.0f / (float)N;
    float mu = s * invN;
    float var = sq * invN - mu * mu;
    float rs = rsqrtf(var + LNEPS);
    float4 gv = ((const float4 *)g)[t];
    float4 bv = ((const float4 *)b)[t];
    v.x = (v.x - mu) * rs * gv.x + bv.x;
    v.y = (v.y - mu) * rs * gv.y + bv.y;
    v.z = (v.z - mu) * rs * gv.z + bv.z;
    v.w = (v.w - mu) * rs * gv.w + bv.w;
    if (DOGELU) {
        v.x = geluf(v.x); v.y = geluf(v.y); v.z = geluf(v.z); v.w = geluf(v.w);
    }
    xr[t] = v;
}

// ---------------- fused attention + 2x LN: writes res1 ----------------
__global__ __launch_bounds__(256) void attn_fused(
    const float *__restrict__ q, const float *__restrict__ k1,
    const float *__restrict__ k2, const float *__restrict__ v1,
    const float *__restrict__ v2, const float *__restrict__ gf,
    const float *__restrict__ f1,
    const float *__restrict__ alng, const float *__restrict__ alnb,
    const float *__restrict__ ln1g, const float *__restrict__ ln1b,
    float *__restrict__ out)
{
    const size_t row = blockIdx.x;
    const size_t base4 = row * (ND / 4);
    const int t = threadIdx.x;

    float s1 = 0.0f, s2 = 0.0f;
#pragma unroll
    for (int p = 0; p < 2; p++) {
        int idx = t + p * 256;
        float4 qv = ((const float4 *)q)[base4 + idx];
        float4 a = ((const float4 *)k1)[base4 + idx];
        float4 b = ((const float4 *)k2)[base4 + idx];
        s1 += qv.x * a.x + qv.y * a.y + qv.z * a.z + qv.w * a.w;
        s2 += qv.x * b.x + qv.y * b.y + qv.z * b.z + qv.w * b.w;
    }
    blockReduce2(s1, s2);
    s1 *= (1.0f / SQRT_D);
    s2 *= (1.0f / SQRT_D);
    float m = fmaxf(s1, s2);
    float e1v = expf(s1 - m), e2v = expf(s2 - m);
    float w1 = e1v / (e1v + e2v), w2 = 1.0f - w1;

    float4 xv[2];
    float s = 0.0f, sq = 0.0f;
#pragma unroll
    for (int p = 0; p < 2; p++) {
        int idx = t + p * 256;
        float4 gv = ((const float4 *)gf)[base4 + idx];
        float4 a = ((const float4 *)v1)[base4 + idx];
        float4 b = ((const float4 *)v2)[base4 + idx];
        float4 x;
        x.x = gv.x + w1 * a.x + w2 * b.x;
        x.y = gv.y + w1 * a.y + w2 * b.y;
        x.z = gv.z + w1 * a.z + w2 * b.z;
        x.w = gv.w + w1 * a.w + w2 * b.w;
        xv[p] = x;
        s += x.x + x.y + x.z + x.w;
        sq += x.x * x.x + x.y * x.y + x.z * x.z + x.w * x.w;
    }
    blockReduce2(s, sq);
    const float invD = 1.0f / (float)ND;
    float mu = s * invD;
    float var = sq * invD - mu * mu;
    float rs = rsqrtf(var + LNEPS);

    float4 yv[2];
    float s3 = 0.0f, sq3 = 0.0f;
#pragma unroll
    for (int p = 0; p < 2; p++) {
        int idx = t + p * 256;
        float4 gv = ((const float4 *)alng)[idx];
        float4 bv = ((const float4 *)alnb)[idx];
        float4 fv = ((const float4 *)f1)[base4 + idx];
        float4 x = xv[p], y;
        y.x = (x.x - mu) * rs * gv.x + bv.x + fv.x;
        y.y = (x.y - mu) * rs * gv.y + bv.y + fv.y;
        y.z = (x.z - mu) * rs * gv.z + bv.z + fv.z;
        y.w = (x.w - mu) * rs * gv.w + bv.w + fv.w;
        yv[p] = y;
        s3 += y.x + y.y + y.z + y.w;
        sq3 += y.x * y.x + y.y * y.y + y.z * y.z + y.w * y.w;
    }
    blockReduce2(s3, sq3);
    float mu2 = s3 * invD;
    float var2 = sq3 * invD - mu2 * mu2;
    float rs2 = rsqrtf(var2 + LNEPS);
#pragma unroll
    for (int p = 0; p < 2; p++) {
        int idx = t + p * 256;
        float4 gv = ((const float4 *)ln1g)[idx];
        float4 bv = ((const float4 *)ln1b)[idx];
        float4 y = yv[p], o;
        o.x = (y.x - mu2) * rs2 * gv.x + bv.x;
        o.y = (y.y - mu2) * rs2 * gv.y + bv.y;
        o.z = (y.z - mu2) * rs2 * gv.z + bv.z;
        o.w = (y.w - mu2) * rs2 * gv.w + bv.w;
        ((float4 *)out)[base4 + idx] = o;
    }
}

// ---------------- aspect BN ----------------
__global__ void bn_count(const int *__restrict__ ids) {
    __shared__ int c[NA];
    if (threadIdx.x < NA) c[threadIdx.x] = 0;
    __syncthreads();
    for (int i = threadIdx.x; i < NB; i += blockDim.x) atomicAdd(&c[ids[i]], 1);
    __syncthreads();
    if (threadIdx.x < NA) g_cnt[threadIdx.x] = c[threadIdx.x];
}

__global__ __launch_bounds__(256) void bn_stats(const float *__restrict__ x,
                                                const int *__restrict__ ids)
{
    __shared__ float ssum[NA][32], ssq[NA][32];
    const int lane = threadIdx.x & 31;
    const int stripe = threadIdx.x >> 5;
    const int c = blockIdx.x * 32 + lane;
    if (stripe == 0) {
#pragma unroll
        for (int a = 0; a < NA; a++) { ssum[a][lane] = 0.0f; ssq[a][lane] = 0.0f; }
    }
    __syncthreads();
    float s0 = 0, s1 = 0, s2 = 0, q0 = 0, q1 = 0, q2 = 0;
#pragma unroll 4
    for (int r = stripe; r < NB; r += 8) {
        int a = ids[r];
        float v = x[(size_t)r * ND + c];
        float vv = v * v;
        if (a == 0) { s0 += v; q0 += vv; }
        else if (a == 1) { s1 += v; q1 += vv; }
        else { s2 += v; q2 += vv; }
    }
    atomicAdd(&ssum[0][lane], s0); atomicAdd(&ssq[0][lane], q0);
    atomicAdd(&ssum[1][lane], s1); atomicAdd(&ssq[1][lane], q1);
    atomicAdd(&ssum[2][lane], s2); atomicAdd(&ssq[2][lane], q2);
    __syncthreads();
    if (stripe < NA) {
        g_bnsum[stripe * ND + c] = ssum[stripe][lane];
        g_bnsq[stripe * ND + c] = ssq[stripe][lane];
    }
}

__global__ void bn_apply(const float *__restrict__ x, const int *__restrict__ ids,
                         const float *__restrict__ bng, const float *__restrict__ bnb,
                         float *__restrict__ out)
{
    const int i = blockIdx.x * blockDim.x + threadIdx.x;
    const int row = i >> 9;
    const int c4 = i & 511;
    const int a = ids[row];
    const int cnt = g_cnt[a];
    float4 v = ((const float4 *)x)[i];
    if (cnt > 1) {
        const float fc = (float)cnt;
        const int cb4 = (a * ND) / 4 + c4;
        float4 sm = ((const float4 *)g_bnsum)[cb4];
        float4 sc = ((const float4 *)g_bnsq)[cb4];
        float4 gv = ((const float4 *)bng)[cb4];
        float4 bv = ((const float4 *)bnb)[cb4];
        float m, vr;
        m = sm.x / fc; vr = sc.x / fc - m * m; v.x = (v.x - m) * rsqrtf(vr + LNEPS) * gv.x + bv.x;
        m = sm.y / fc; vr = sc.y / fc - m * m; v.y = (v.y - m) * rsqrtf(vr + LNEPS) * gv.y + bv.y;
        m = sm.z / fc; vr = sc.z / fc - m * m; v.z = (v.z - m) * rsqrtf(vr + LNEPS) * gv.z + bv.z;
        m = sm.w / fc; vr = sc.w / fc - m * m; v.w = (v.w - m) * rsqrtf(vr + LNEPS) * gv.w + bv.w;
    }
    ((float4 *)out)[i] = v;
}

// ---------------- final LN(a + b) -> out ----------------
__global__ __launch_bounds__(256) void ln_residual(
    const float *__restrict__ x, const float *__restrict__ res,
    const float *__restrict__ g, const float *__restrict__ b,
    float *__restrict__ out)
{
    const size_t base4 = (size_t)blockIdx.x * (ND / 4);
    const int t = threadIdx.x;
    float4 v[2];
    float s = 0.0f, sq = 0.0f;
#pragma unroll
    for (int p = 0; p < 2; p++) {
        int idx = t + p * 256;
        float4 a = ((const float4 *)x)[base4 + idx];
        float4 r = ((const float4 *)res)[base4 + idx];
        a.x += r.x; a.y += r.y; a.z += r.z; a.w += r.w;
        v[p] = a;
        s += a.x + a.y + a.z + a.w;
        sq += a.x * a.x + a.y * a.y + a.z * a.z + a.w * a.w;
    }
    blockReduce2(s, sq);
    const float invD = 1.0f / (float)ND;
    float mu = s * invD;
    float var = sq * invD - mu * mu;
    float rs = rsqrtf(var + LNEPS);
#pragma unroll
    for (int p = 0; p < 2; p++) {
        int idx = t + p * 256;
        float4 gv = ((const float4 *)g)[idx];
        float4 bv = ((const float4 *)b)[idx];
        float4 a = v[p], o;
        o.x = (a.x - mu) * rs * gv.x + bv.x;
        o.y = (a.y - mu) * rs * gv.y + bv.y;
        o.z = (a.z - mu) * rs * gv.z + bv.z;
        o.w = (a.w - mu) * rs * gv.w + bv.w;
        ((float4 *)out)[base4 + idx] = o;
    }
}

// ---------------- launch ----------------
extern "C" void kernel_launch(void *const *d_in, const int *in_sizes, int n_in,
                              void *d_out, int out_size)
{
    const float *f1 = (const float *)d_in[0];
    const float *f2 = (const float *)d_in[1];
    const int *ids = (const int *)d_in[2];
    const float *gW1 = (const float *)d_in[3], *gb1 = (const float *)d_in[4];
    const float *gl1g = (const float *)d_in[5], *gl1b = (const float *)d_in[6];
    const float *gW2 = (const float *)d_in[7], *gb2 = (const float *)d_in[8];
    const float *gl2g = (const float *)d_in[9], *gl2b = (const float *)d_in[10];
    const float *gW3 = (const float *)d_in[11], *gb3 = (const float *)d_in[12];
    const float *qW = (const float *)d_in[13], *qb = (const float *)d_in[14];
    const float *kW = (const float *)d_in[15], *kb = (const float *)d_in[16];
    const float *vW = (const float *)d_in[17], *vb = (const float *)d_in[18];
    const float *alng = (const float *)d_in[19], *alnb = (const float *)d_in[20];
    const float *bng = (const float *)d_in[21], *bnb = (const float *)d_in[22];
    const float *ln1g = (const float *)d_in[23], *ln1b = (const float *)d_in[24];
    const float *fW1 = (const float *)d_in[25], *fb1 = (const float *)d_in[26];
    const float *fW2 = (const float *)d_in[27], *fb2 = (const float *)d_in[28];
    const float *ln2g = (const float *)d_in[29], *ln2b = (const float *)d_in[30];
    float *out = (float *)d_out;

    float *h1, *h2, *gf, *q, *k1, *k2, *v1, *v2, *res1, *nrm, *mid, *wt;
    cudaGetSymbolAddress((void **)&h1, g_h1);
    cudaGetSymbolAddress((void **)&h2, g_h2);
    cudaGetSymbolAddress((void **)&gf, g_gf);
    cudaGetSymbolAddress((void **)&q, g_q);
    cudaGetSymbolAddress((void **)&k1, g_k1);
    cudaGetSymbolAddress((void **)&k2, g_k2);
    cudaGetSymbolAddress((void **)&v1, g_v1);
    cudaGetSymbolAddress((void **)&v2, g_v2);
    cudaGetSymbolAddress((void **)&res1, g_res1);
    cudaGetSymbolAddress((void **)&nrm, g_norm);
    cudaGetSymbolAddress((void **)&mid, g_mid);
    cudaGetSymbolAddress((void **)&wt, g_wt);

    cudaFuncSetAttribute(tgemm<0>, cudaFuncAttributeMaxDynamicSharedMemorySize, SM_TOTAL);
    cudaFuncSetAttribute(tgemm<1>, cudaFuncAttributeMaxDynamicSharedMemorySize, SM_TOTAL);
    cudaFuncSetAttribute(tgemm<2>, cudaFuncAttributeMaxDynamicSharedMemorySize, SM_TOTAL);

    // transpose all weights [K,N] -> [N,K]
    dim3 tb(32, 8);
    transp<<<dim3(512 / 32, 4096 / 32), tb>>>(gW1, wt + OF_GW1T, 4096, 512);
    transp<<<dim3(256 / 32, 512 / 32), tb>>>(gW2, wt + OF_GW2T, 512, 256);
    transp<<<dim3(2048 / 32, 256 / 32), tb>>>(gW3, wt + OF_GW3T, 256, 2048);
    transp<<<dim3(2048 / 32, 2048 / 32), tb>>>(qW, wt + OF_QWT, 2048, 2048);
    transp<<<dim3(2048 / 32, 2048 / 32), tb>>>(kW, wt + OF_KWT, 2048, 2048);
    transp<<<dim3(2048 / 32, 2048 / 32), tb>>>(vW, wt + OF_VWT, 2048, 2048);
    transp<<<dim3(4096 / 32, 2048 / 32), tb>>>(fW1, wt + OF_FW1T, 2048, 4096);
    transp<<<dim3(2048 / 32, 4096 / 32), tb>>>(fW2, wt + OF_FW2T, 4096, 2048);

    const dim3 gG1(NH / GT_N, NB / GT_M);       // 4 x 64
    const dim3 gG2((NH / 2) / GT_N, NB / GT_M); // 2 x 64
    const dim3 gD(ND / GT_N, NB / GT_M);        // 16 x 64
    const dim3 g2D((2 * ND) / GT_N, NB / GT_M); // 32 x 64

    // gate MLP layer 1 (concat K over f1,f2)
    tgemm<0><<<gG1, 256, SM_TOTAL>>>(f1, f2, wt + OF_GW1T, gb1, h1,
                                     NB, NH, ND, ND, nullptr, nullptr);
    ln_act<true><<<NB, NH / 4>>>(h1, gl1g, gl1b, NH);
    tgemm<0><<<gG2, 256, SM_TOTAL>>>(h1, h1, wt + OF_GW2T, gb2, h2,
                                     NB, NH / 2, NH, 0, nullptr, nullptr);
    ln_act<true><<<NB, (NH / 2) / 4>>>(h2, gl2g, gl2b, NH / 2);
    tgemm<2><<<gD, 256, SM_TOTAL>>>(h2, h2, wt + OF_GW3T, gb3, gf,
                                    NB, ND, NH / 2, 0, f1, f2);
    tgemm<0><<<gD, 256, SM_TOTAL>>>(gf, gf, wt + OF_QWT, qb, q, NB, ND, ND, 0, nullptr, nullptr);
    tgemm<0><<<gD, 256, SM_TOTAL>>>(f1, f1, wt + OF_KWT, kb, k1, NB, ND, ND, 0, nullptr, nullptr);
    tgemm<0><<<gD, 256, SM_TOTAL>>>(f2, f2, wt + OF_KWT, kb, k2, NB, ND, ND, 0, nullptr, nullptr);
    tgemm<0><<<gD, 256, SM_TOTAL>>>(f1, f1, wt + OF_VWT, vb, v1, NB, ND, ND, 0, nullptr, nullptr);
    tgemm<0><<<gD, 256, SM_TOTAL>>>(f2, f2, wt + OF_VWT, vb, v2, NB, ND, ND, 0, nullptr, nullptr);
    attn_fused<<<NB, 256>>>(q, k1, k2, v1, v2, gf, f1, alng, alnb, ln1g, ln1b, res1);
    bn_count<<<1, 256>>>(ids);
    bn_stats<<<ND / 32, 256>>>(res1, ids);
    bn_apply<<<(NB * ND / 4) / 256, 256>>>(res1, ids, bng, bnb, nrm);
    tgemm<1><<<g2D, 256, SM_TOTAL>>>(nrm, nrm, wt + OF_FW1T, fb1, mid,
                                     NB, 2 * ND, ND, 0, nullptr, nullptr);
    tgemm<0><<<gD, 256, SM_TOTAL>>>(mid, mid, wt + OF_FW2T, fb2, q,
                                    NB, ND, 2 * ND, 0, nullptr, nullptr);
    ln_residual<<<NB, 256>>>(q, nrm, ln2g, ln2b, out);
}

// round 5
// speedup vs baseline: 4.7484x; 1.1073x over previous
#include <cuda_runtime.h>
#include <cuda_fp16.h>
#include <math.h>
#include <stdint.h>

#define NB 8192
#define ND 2048
#define NH 512
#define NA 3
#define LNEPS 1e-5f
#define SQRT_D 45.25483399593904f

// ---------------- scratch (device globals; no allocation allowed) ----------
__device__ float g_h1[(size_t)NB * NH];
__device__ float g_h2[(size_t)NB * (NH / 2)];
__device__ float g_gf[(size_t)NB * ND];
__device__ float g_q[(size_t)NB * ND];
__device__ float g_k1[(size_t)NB * ND];
__device__ float g_k2[(size_t)NB * ND];
__device__ float g_v1[(size_t)NB * ND];
__device__ float g_v2[(size_t)NB * ND];
__device__ float g_res1[(size_t)NB * ND];
__device__ float g_norm[(size_t)NB * ND];
__device__ float g_bnsum[NA * ND];
__device__ float g_bnsq[NA * ND];
__device__ int   g_cnt[NA];
// half activation buffers
__device__ __half g_f1h[(size_t)NB * ND];
__device__ __half g_f2h[(size_t)NB * ND];
__device__ __half g_h1h[(size_t)NB * NH];
__device__ __half g_h2h[(size_t)NB * (NH / 2)];
__device__ __half g_gfh[(size_t)NB * ND];
__device__ __half g_nrmh[(size_t)NB * ND];
__device__ __half g_midh[(size_t)NB * 2 * ND];
// half transposed weights
__device__ __half g_wth[32112640];

#define OF_GW1T 0
#define OF_GW2T (OF_GW1T + 4096 * 512)
#define OF_GW3T (OF_GW2T + 512 * 256)
#define OF_QWT  (OF_GW3T + 256 * 2048)
#define OF_KWT  (OF_QWT + 2048 * 2048)
#define OF_VWT  (OF_KWT + 2048 * 2048)
#define OF_FW1T (OF_VWT + 2048 * 2048)
#define OF_FW2T (OF_FW1T + 2048 * 4096)

// ---------------- helpers ----------------
__device__ __forceinline__ float geluf(float x) {
    return 0.5f * x * (1.0f + erff(x * 0.70710678118654752f));
}
__device__ __forceinline__ uint32_t smem_u32(const void *p) {
    uint32_t a;
    asm("{ .reg .u64 t; cvta.to.shared.u64 t, %1; cvt.u32.u64 %0, t; }" : "=r"(a) : "l"(p));
    return a;
}
__device__ __forceinline__ uint32_t swz128(uint32_t off) {
    return off ^ ((off >> 3) & 0x70u);
}
__device__ __forceinline__ void cp16(uint32_t s, const void *g) {
    asm volatile("cp.async.cg.shared.global [%0], [%1], 16;" :: "r"(s), "l"(g));
}
__device__ __forceinline__ void cp_commit() { asm volatile("cp.async.commit_group;" ::: "memory"); }
template <int N> __device__ __forceinline__ void cp_wait() {
    asm volatile("cp.async.wait_group %0;" :: "n"(N) : "memory");
}
__device__ __forceinline__ void ldsm4(uint32_t *r, uint32_t addr) {
    asm volatile("ldmatrix.sync.aligned.m8n8.x4.shared.b16 {%0,%1,%2,%3}, [%4];"
                 : "=r"(r[0]), "=r"(r[1]), "=r"(r[2]), "=r"(r[3]) : "r"(addr));
}
__device__ __forceinline__ void mma16816(float *c, const uint32_t *a, const uint32_t *b) {
    asm volatile(
        "mma.sync.aligned.m16n8k16.row.col.f32.f16.f16.f32 "
        "{%0,%1,%2,%3}, {%4,%5,%6,%7}, {%8,%9}, {%0,%1,%2,%3};"
        : "+f"(c[0]), "+f"(c[1]), "+f"(c[2]), "+f"(c[3])
        : "r"(a[0]), "r"(a[1]), "r"(a[2]), "r"(a[3]), "r"(b[0]), "r"(b[1]));
}

// two-value block reduction (sum); result broadcast to all threads
__device__ __forceinline__ void blockReduce2(float &a, float &b) {
    __shared__ float sa[32], sb[32];
#pragma unroll
    for (int o = 16; o; o >>= 1) {
        a += __shfl_xor_sync(0xFFFFFFFFu, a, o);
        b += __shfl_xor_sync(0xFFFFFFFFu, b, o);
    }
    const int lane = threadIdx.x & 31, w = threadIdx.x >> 5;
    const int nw = blockDim.x >> 5;
    if (nw > 1) {
        if (lane == 0) { sa[w] = a; sb[w] = b; }
        __syncthreads();
        a = (lane < nw) ? sa[lane] : 0.0f;
        b = (lane < nw) ? sb[lane] : 0.0f;
#pragma unroll
        for (int o = 16; o; o >>= 1) {
            a += __shfl_xor_sync(0xFFFFFFFFu, a, o);
            b += __shfl_xor_sync(0xFFFFFFFFu, b, o);
        }
        __syncthreads();
    }
}

// ---------------- weight transpose + f32->f16: in[K,N] -> out[N,K] --------
__global__ void transp(const float *__restrict__ in, __half *__restrict__ out,
                       int K, int N) {
    __shared__ float t[32][33];
    const int n0 = blockIdx.x * 32, k0 = blockIdx.y * 32;
#pragma unroll
    for (int i = threadIdx.y; i < 32; i += 8)
        t[i][threadIdx.x] = in[(size_t)(k0 + i) * N + n0 + threadIdx.x];
    __syncthreads();
#pragma unroll
    for (int i = threadIdx.y; i < 32; i += 8)
        out[(size_t)(n0 + i) * K + k0 + threadIdx.x] =
            __float2half_rn(t[threadIdx.x][i]);
}

// ---------------- f32 -> f16 convert ----------------
__global__ void cvt_half(const float4 *__restrict__ in, __half2 *__restrict__ out,
                         int n4) {
    int i = blockIdx.x * blockDim.x + threadIdx.x;
    if (i < n4) {
        float4 v = in[i];
        out[2 * i]     = __floats2half2_rn(v.x, v.y);
        out[2 * i + 1] = __floats2half2_rn(v.z, v.w);
    }
}

// ---------------- fp16 GEMM: C = concat_K(A1,A2) @ WT^T + bias -------------
// A half [M,K] row-major, WT half [N,K] K-major. CTA 128x128, k-chunk 64.
// EPI: 0 = bias, 1 = bias+gelu, 2 = bias+sigmoid gate combine e1/e2
// C (fp32) and Ch (half) outputs each optional (null = skip).
#define GT_M 128
#define GT_N 128
#define GKH 64
#define SMA_SZ (GT_M * GKH * 2)         // 16384
#define SMBUF  (2 * SMA_SZ)             // 32768
#define SM_TOTAL (1024 + 2 * SMBUF)     // 66560

template <int EPI>
__global__ __launch_bounds__(256) void tgemm(
    const __half *__restrict__ A1, const __half *__restrict__ A2,
    const __half *__restrict__ WT, const float *__restrict__ bias,
    float *__restrict__ C, __half *__restrict__ Ch,
    int M, int N, int K1, int K2,
    const float *__restrict__ e1, const float *__restrict__ e2)
{
    extern __shared__ char smem[];
    const uint32_t sb = smem_u32(smem);
    const uint32_t tile0 = (sb + 1023) & ~1023u;
    const int tid = threadIdx.x;
    const int wid = tid >> 5, lane = tid & 31;
    const size_t rowBase = (size_t)blockIdx.y * GT_M;
    const size_t colBase = (size_t)blockIdx.x * GT_N;
    const int K = K1 + K2;
    const int niter = K / GKH;

    const int warpM = (wid >> 1) * 32, warpN = (wid & 1) * 64;

    // cp.async chunk mapping: 16B chunks, 8 per 128B row; A:4/thread, B:4/thread
    uint32_t aoff[4], boff[4];
    const __half *pA1[4], *pA2[4], *pB[4];
#pragma unroll
    for (int i = 0; i < 4; i++) {
        int c = tid + i * 256, r = c >> 3, k16 = c & 7;
        aoff[i] = swz128((uint32_t)(r * 128 + k16 * 16));
        pA1[i] = A1 + (rowBase + r) * (size_t)K1 + k16 * 8;
        pA2[i] = A2 + (rowBase + r) * (size_t)K2 + k16 * 8 - K1;
        boff[i] = SMA_SZ + aoff[i];
        pB[i] = WT + (colBase + r) * (size_t)K + k16 * 8;
    }

    // ldmatrix per-lane relative base addresses (swizzle pre-applied)
    // A frag (m16k16): lanes 0-7: m0-7@k0 | 8-15: m8-15@k0 | 16-23: m0-7@k8 | 24-31: m8-15@k8
    uint32_t aBase[2];
    {
        uint32_t khiA = ((lane >> 4) & 1) * 16;
#pragma unroll
        for (int mt = 0; mt < 2; mt++) {
            int r = warpM + mt * 16 + (lane & 15);
            aBase[mt] = ((uint32_t)(r * 128 + ((r & 7) << 4))) ^ khiA;
        }
    }
    // B frags (two n8k16 per x4): lanes 0-7: n0-7@k0 | 8-15: n0-7@k8 | 16-23: n8-15@k0 | 24-31: n8-15@k8
    uint32_t bBase[4];
    {
        uint32_t khiB = ((lane >> 3) & 1) * 16;
#pragma unroll
        for (int p = 0; p < 4; p++) {
            int r = warpN + p * 16 + ((lane >> 4) & 1) * 8 + (lane & 7);
            bBase[p] = ((uint32_t)(r * 128 + ((r & 7) << 4))) ^ khiB;
        }
    }

    float acc[2][8][4];
#pragma unroll
    for (int mt = 0; mt < 2; mt++)
#pragma unroll
        for (int nt = 0; nt < 8; nt++)
#pragma unroll
            for (int j = 0; j < 4; j++) acc[mt][nt][j] = 0.0f;

    // prologue into buffer 0
#pragma unroll
    for (int i = 0; i < 4; i++) cp16(tile0 + aoff[i], pA1[i]);
#pragma unroll
    for (int i = 0; i < 4; i++) cp16(tile0 + boff[i], pB[i]);
    cp_commit();

    for (int it = 0; it < niter; ++it) {
        const int b = it & 1;
        if (it + 1 < niter) {
            const int nb = b ^ 1;
            const int kg = (it + 1) * GKH;
            const uint32_t tb = tile0 + nb * SMBUF;
            const bool s1 = kg < K1;
#pragma unroll
            for (int i = 0; i < 4; i++)
                cp16(tb + aoff[i], (s1 ? pA1[i] : pA2[i]) + kg);
#pragma unroll
            for (int i = 0; i < 4; i++) cp16(tb + boff[i], pB[i] + kg);
            cp_commit();
            cp_wait<1>();
        } else {
            cp_wait<0>();
        }
        __syncthreads();
        const uint32_t tA = tile0 + b * SMBUF;
        const uint32_t tB = tA + SMA_SZ;
#pragma unroll
        for (int k16 = 0; k16 < GKH / 16; ++k16) {
            const uint32_t kb2 = k16 * 32;
            uint32_t a[2][4];
            ldsm4(a[0], tA + (aBase[0] ^ kb2));
            ldsm4(a[1], tA + (aBase[1] ^ kb2));
            uint32_t bf[4][4];
#pragma unroll
            for (int p = 0; p < 4; p++) ldsm4(bf[p], tB + (bBase[p] ^ kb2));
#pragma unroll
            for (int mt = 0; mt < 2; mt++)
#pragma unroll
                for (int p = 0; p < 4; p++) {
                    mma16816(acc[mt][2 * p], a[mt], &bf[p][0]);
                    mma16816(acc[mt][2 * p + 1], a[mt], &bf[p][2]);
                }
        }
        __syncthreads();
    }

    // epilogue
#pragma unroll
    for (int mt = 0; mt < 2; mt++) {
#pragma unroll
        for (int hf = 0; hf < 2; hf++) {
            const size_t m = rowBase + warpM + mt * 16 + (lane >> 2) + hf * 8;
            const size_t crow = m * (size_t)N;
#pragma unroll
            for (int nt = 0; nt < 8; nt++) {
                const size_t c0 = colBase + warpN + nt * 8 + (lane & 3) * 2;
                float v0 = acc[mt][nt][hf * 2 + 0] + bias[c0];
                float v1 = acc[mt][nt][hf * 2 + 1] + bias[c0 + 1];
                if (EPI == 1) { v0 = geluf(v0); v1 = geluf(v1); }
                if (EPI == 2) {
                    float s0 = 1.0f / (1.0f + expf(-v0));
                    float s1 = 1.0f / (1.0f + expf(-v1));
                    v0 = s0 * e1[crow + c0] + (1.0f - s0) * e2[crow + c0];
                    v1 = s1 * e1[crow + c0 + 1] + (1.0f - s1) * e2[crow + c0 + 1];
                }
                if (C) *(float2 *)(C + crow + c0) = make_float2(v0, v1);
                if (Ch) *(__half2 *)(Ch + crow + c0) = __floats2half2_rn(v0, v1);
            }
        }
    }
}

// ---------------- LN + exact GELU -> half out ----------------
__global__ void ln_gelu_h(const float *__restrict__ x, const float *__restrict__ g,
                          const float *__restrict__ b, __half *__restrict__ xh, int N)
{
    const size_t row = blockIdx.x;
    const float4 *xr = (const float4 *)(x + row * (size_t)N);
    const int t = threadIdx.x;
    float4 v = xr[t];
    float s = v.x + v.y + v.z + v.w;
    float sq = v.x * v.x + v.y * v.y + v.z * v.z + v.w * v.w;
    blockReduce2(s, sq);
    const float invN = 1.0f / (float)N;
    float mu = s * invN;
    float var = sq * invN - mu * mu;
    float rs = rsqrtf(var + LNEPS);
    float4 gv = ((const float4 *)g)[t];
    float4 bv = ((const float4 *)b)[t];
    v.x = geluf((v.x - mu) * rs * gv.x + bv.x);
    v.y = geluf((v.y - mu) * rs * gv.y + bv.y);
    v.z = geluf((v.z - mu) * rs * gv.z + bv.z);
    v.w = geluf((v.w - mu) * rs * gv.w + bv.w);
    __half2 *ho = (__half2 *)(xh + row * (size_t)N);
    ho[2 * t] = __floats2half2_rn(v.x, v.y);
    ho[2 * t + 1] = __floats2half2_rn(v.z, v.w);
}

// ---------------- fused attention + 2x LN: writes res1 ----------------
__global__ __launch_bounds__(256) void attn_fused(
    const float *__restrict__ q, const float *__restrict__ k1,
    const float *__restrict__ k2, const float *__restrict__ v1,
    const float *__restrict__ v2, const float *__restrict__ gf,
    const float *__restrict__ f1,
    const float *__restrict__ alng, const float *__restrict__ alnb,
    const float *__restrict__ ln1g, const float *__restrict__ ln1b,
    float *__restrict__ out)
{
    const size_t row = blockIdx.x;
    const size_t base4 = row * (ND / 4);
    const int t = threadIdx.x;

    float s1 = 0.0f, s2 = 0.0f;
#pragma unroll
    for (int p = 0; p < 2; p++) {
        int idx = t + p * 256;
        float4 qv = ((const float4 *)q)[base4 + idx];
        float4 a = ((const float4 *)k1)[base4 + idx];
        float4 b = ((const float4 *)k2)[base4 + idx];
        s1 += qv.x * a.x + qv.y * a.y + qv.z * a.z + qv.w * a.w;
        s2 += qv.x * b.x + qv.y * b.y + qv.z * b.z + qv.w * b.w;
    }
    blockReduce2(s1, s2);
    s1 *= (1.0f / SQRT_D);
    s2 *= (1.0f / SQRT_D);
    float m = fmaxf(s1, s2);
    float e1v = expf(s1 - m), e2v = expf(s2 - m);
    float w1 = e1v / (e1v + e2v), w2 = 1.0f - w1;

    float4 xv[2];
    float s = 0.0f, sq = 0.0f;
#pragma unroll
    for (int p = 0; p < 2; p++) {
        int idx = t + p * 256;
        float4 gv = ((const float4 *)gf)[base4 + idx];
        float4 a = ((const float4 *)v1)[base4 + idx];
        float4 b = ((const float4 *)v2)[base4 + idx];
        float4 x;
        x.x = gv.x + w1 * a.x + w2 * b.x;
        x.y = gv.y + w1 * a.y + w2 * b.y;
        x.z = gv.z + w1 * a.z + w2 * b.z;
        x.w = gv.w + w1 * a.w + w2 * b.w;
        xv[p] = x;
        s += x.x + x.y + x.z + x.w;
        sq += x.x * x.x + x.y * x.y + x.z * x.z + x.w * x.w;
    }
    blockReduce2(s, sq);
    const float invD = 1.0f / (float)ND;
    float mu = s * invD;
    float var = sq * invD - mu * mu;
    float rs = rsqrtf(var + LNEPS);

    float4 yv[2];
    float s3 = 0.0f, sq3 = 0.0f;
#pragma unroll
    for (int p = 0; p < 2; p++) {
        int idx = t + p * 256;
        float4 gv = ((const float4 *)alng)[idx];
        float4 bv = ((const float4 *)alnb)[idx];
        float4 fv = ((const float4 *)f1)[base4 + idx];
        float4 x = xv[p], y;
        y.x = (x.x - mu) * rs * gv.x + bv.x + fv.x;
        y.y = (x.y - mu) * rs * gv.y + bv.y + fv.y;
        y.z = (x.z - mu) * rs * gv.z + bv.z + fv.z;
        y.w = (x.w - mu) * rs * gv.w + bv.w + fv.w;
        yv[p] = y;
        s3 += y.x + y.y + y.z + y.w;
        sq3 += y.x * y.x + y.y * y.y + y.z * y.z + y.w * y.w;
    }
    blockReduce2(s3, sq3);
    float mu2 = s3 * invD;
    float var2 = sq3 * invD - mu2 * mu2;
    float rs2 = rsqrtf(var2 + LNEPS);
#pragma unroll
    for (int p = 0; p < 2; p++) {
        int idx = t + p * 256;
        float4 gv = ((const float4 *)ln1g)[idx];
        float4 bv = ((const float4 *)ln1b)[idx];
        float4 y = yv[p], o;
        o.x = (y.x - mu2) * rs2 * gv.x + bv.x;
        o.y = (y.y - mu2) * rs2 * gv.y + bv.y;
        o.z = (y.z - mu2) * rs2 * gv.z + bv.z;
        o.w = (y.w - mu2) * rs2 * gv.w + bv.w;
        ((float4 *)out)[base4 + idx] = o;
    }
}

// ---------------- aspect BN ----------------
__global__ void bn_count(const int *__restrict__ ids) {
    __shared__ int c[NA];
    if (threadIdx.x < NA) c[threadIdx.x] = 0;
    __syncthreads();
    for (int i = threadIdx.x; i < NB; i += blockDim.x) atomicAdd(&c[ids[i]], 1);
    __syncthreads();
    if (threadIdx.x < NA) g_cnt[threadIdx.x] = c[threadIdx.x];
}

__global__ __launch_bounds__(256) void bn_stats(const float *__restrict__ x,
                                                const int *__restrict__ ids)
{
    __shared__ float ssum[NA][32], ssq[NA][32];
    const int lane = threadIdx.x & 31;
    const int stripe = threadIdx.x >> 5;
    const int c = blockIdx.x * 32 + lane;
    if (stripe == 0) {
#pragma unroll
        for (int a = 0; a < NA; a++) { ssum[a][lane] = 0.0f; ssq[a][lane] = 0.0f; }
    }
    __syncthreads();
    float s0 = 0, s1 = 0, s2 = 0, q0 = 0, q1 = 0, q2 = 0;
#pragma unroll 4
    for (int r = stripe; r < NB; r += 8) {
        int a = ids[r];
        float v = x[(size_t)r * ND + c];
        float vv = v * v;
        if (a == 0) { s0 += v; q0 += vv; }
        else if (a == 1) { s1 += v; q1 += vv; }
        else { s2 += v; q2 += vv; }
    }
    atomicAdd(&ssum[0][lane], s0); atomicAdd(&ssq[0][lane], q0);
    atomicAdd(&ssum[1][lane], s1); atomicAdd(&ssq[1][lane], q1);
    atomicAdd(&ssum[2][lane], s2); atomicAdd(&ssq[2][lane], q2);
    __syncthreads();
    if (stripe < NA) {
        g_bnsum[stripe * ND + c] = ssum[stripe][lane];
        g_bnsq[stripe * ND + c] = ssq[stripe][lane];
    }
}

__global__ void bn_apply(const float *__restrict__ x, const int *__restrict__ ids,
                         const float *__restrict__ bng, const float *__restrict__ bnb,
                         float *__restrict__ out, __half *__restrict__ outh)
{
    const int i = blockIdx.x * blockDim.x + threadIdx.x;
    const int row = i >> 9;
    const int c4 = i & 511;
    const int a = ids[row];
    const int cnt = g_cnt[a];
    float4 v = ((const float4 *)x)[i];
    if (cnt > 1) {
        const float fc = (float)cnt;
        const int cb4 = (a * ND) / 4 + c4;
        float4 sm = ((const float4 *)g_bnsum)[cb4];
        float4 sc = ((const float4 *)g_bnsq)[cb4];
        float4 gv = ((const float4 *)bng)[cb4];
        float4 bv = ((const float4 *)bnb)[cb4];
        float m, vr;
        m = sm.x / fc; vr = sc.x / fc - m * m; v.x = (v.x - m) * rsqrtf(vr + LNEPS) * gv.x + bv.x;
        m = sm.y / fc; vr = sc.y / fc - m * m; v.y = (v.y - m) * rsqrtf(vr + LNEPS) * gv.y + bv.y;
        m = sm.z / fc; vr = sc.z / fc - m * m; v.z = (v.z - m) * rsqrtf(vr + LNEPS) * gv.z + bv.z;
        m = sm.w / fc; vr = sc.w / fc - m * m; v.w = (v.w - m) * rsqrtf(vr + LNEPS) * gv.w + bv.w;
    }
    ((float4 *)out)[i] = v;
    __half2 *ho = (__half2 *)outh;
    ho[2 * i] = __floats2half2_rn(v.x, v.y);
    ho[2 * i + 1] = __floats2half2_rn(v.z, v.w);
}

// ---------------- final LN(a + b) -> out ----------------
__global__ __launch_bounds__(256) void ln_residual(
    const float *__restrict__ x, const float *__restrict__ res,
    const float *__restrict__ g, const float *__restrict__ b,
    float *__restrict__ out)
{
    const size_t base4 = (size_t)blockIdx.x * (ND / 4);
    const int t = threadIdx.x;
    float4 v[2];
    float s = 0.0f, sq = 0.0f;
#pragma unroll
    for (int p = 0; p < 2; p++) {
        int idx = t + p * 256;
        float4 a = ((const float4 *)x)[base4 + idx];
        float4 r = ((const float4 *)res)[base4 + idx];
        a.x += r.x; a.y += r.y; a.z += r.z; a.w += r.w;
        v[p] = a;
        s += a.x + a.y + a.z + a.w;
        sq += a.x * a.x + a.y * a.y + a.z * a.z + a.w * a.w;
    }
    blockReduce2(s, sq);
    const float invD = 1.0f / (float)ND;
    float mu = s * invD;
    float var = sq * invD - mu * mu;
    float rs = rsqrtf(var + LNEPS);
#pragma unroll
    for (int p = 0; p < 2; p++) {
        int idx = t + p * 256;
        float4 gv = ((const float4 *)g)[idx];
        float4 bv = ((const float4 *)b)[idx];
        float4 a = v[p], o;
        o.x = (a.x - mu) * rs * gv.x + bv.x;
        o.y = (a.y - mu) * rs * gv.y + bv.y;
        o.z = (a.z - mu) * rs * gv.z + bv.z;
        o.w = (a.w - mu) * rs * gv.w + bv.w;
        ((float4 *)out)[base4 + idx] = o;
    }
}

// ---------------- launch ----------------
extern "C" void kernel_launch(void *const *d_in, const int *in_sizes, int n_in,
                              void *d_out, int out_size)
{
    const float *f1 = (const float *)d_in[0];
    const float *f2 = (const float *)d_in[1];
    const int *ids = (const int *)d_in[2];
    const float *gW1 = (const float *)d_in[3], *gb1 = (const float *)d_in[4];
    const float *gl1g = (const float *)d_in[5], *gl1b = (const float *)d_in[6];
    const float *gW2 = (const float *)d_in[7], *gb2 = (const float *)d_in[8];
    const float *gl2g = (const float *)d_in[9], *gl2b = (const float *)d_in[10];
    const float *gW3 = (const float *)d_in[11], *gb3 = (const float *)d_in[12];
    const float *qW = (const float *)d_in[13], *qb = (const float *)d_in[14];
    const float *kW = (const float *)d_in[15], *kb = (const float *)d_in[16];
    const float *vW = (const float *)d_in[17], *vb = (const float *)d_in[18];
    const float *alng = (const float *)d_in[19], *alnb = (const float *)d_in[20];
    const float *bng = (const float *)d_in[21], *bnb = (const float *)d_in[22];
    const float *ln1g = (const float *)d_in[23], *ln1b = (const float *)d_in[24];
    const float *fW1 = (const float *)d_in[25], *fb1 = (const float *)d_in[26];
    const float *fW2 = (const float *)d_in[27], *fb2 = (const float *)d_in[28];
    const float *ln2g = (const float *)d_in[29], *ln2b = (const float *)d_in[30];
    float *out = (float *)d_out;

    float *h1, *h2, *gf, *q, *k1, *k2, *v1, *v2, *res1, *nrm;
    __half *f1h, *f2h, *h1h, *h2h, *gfh, *nrmh, *midh, *wth;
    cudaGetSymbolAddress((void **)&h1, g_h1);
    cudaGetSymbolAddress((void **)&h2, g_h2);
    cudaGetSymbolAddress((void **)&gf, g_gf);
    cudaGetSymbolAddress((void **)&q, g_q);
    cudaGetSymbolAddress((void **)&k1, g_k1);
    cudaGetSymbolAddress((void **)&k2, g_k2);
    cudaGetSymbolAddress((void **)&v1, g_v1);
    cudaGetSymbolAddress((void **)&v2, g_v2);
    cudaGetSymbolAddress((void **)&res1, g_res1);
    cudaGetSymbolAddress((void **)&nrm, g_norm);
    cudaGetSymbolAddress((void **)&f1h, g_f1h);
    cudaGetSymbolAddress((void **)&f2h, g_f2h);
    cudaGetSymbolAddress((void **)&h1h, g_h1h);
    cudaGetSymbolAddress((void **)&h2h, g_h2h);
    cudaGetSymbolAddress((void **)&gfh, g_gfh);
    cudaGetSymbolAddress((void **)&nrmh, g_nrmh);
    cudaGetSymbolAddress((void **)&midh, g_midh);
    cudaGetSymbolAddress((void **)&wth, g_wth);

    cudaFuncSetAttribute(tgemm<0>, cudaFuncAttributeMaxDynamicSharedMemorySize, SM_TOTAL);
    cudaFuncSetAttribute(tgemm<1>, cudaFuncAttributeMaxDynamicSharedMemorySize, SM_TOTAL);
    cudaFuncSetAttribute(tgemm<2>, cudaFuncAttributeMaxDynamicSharedMemorySize, SM_TOTAL);

    // transpose + f16-convert all weights [K,N] -> [N,K]
    dim3 tb(32, 8);
    transp<<<dim3(512 / 32, 4096 / 32), tb>>>(gW1, wth + OF_GW1T, 4096, 512);
    transp<<<dim3(256 / 32, 512 / 32), tb>>>(gW2, wth + OF_GW2T, 512, 256);
    transp<<<dim3(2048 / 32, 256 / 32), tb>>>(gW3, wth + OF_GW3T, 256, 2048);
    transp<<<dim3(2048 / 32, 2048 / 32), tb>>>(qW, wth + OF_QWT, 2048, 2048);
    transp<<<dim3(2048 / 32, 2048 / 32), tb>>>(kW, wth + OF_KWT, 2048, 2048);
    transp<<<dim3(2048 / 32, 2048 / 32), tb>>>(vW, wth + OF_VWT, 2048, 2048);
    transp<<<dim3(4096 / 32, 2048 / 32), tb>>>(fW1, wth + OF_FW1T, 2048, 4096);
    transp<<<dim3(2048 / 32, 4096 / 32), tb>>>(fW2, wth + OF_FW2T, 4096, 2048);
    // f1/f2 -> half
    cvt_half<<<(NB * ND / 4) / 256, 256>>>((const float4 *)f1, (__half2 *)f1h, NB * ND / 4);
    cvt_half<<<(NB * ND / 4) / 256, 256>>>((const float4 *)f2, (__half2 *)f2h, NB * ND / 4);

    const dim3 gG1(NH / GT_N, NB / GT_M);
    const dim3 gG2((NH / 2) / GT_N, NB / GT_M);
    const dim3 gD(ND / GT_N, NB / GT_M);
    const dim3 g2D((2 * ND) / GT_N, NB / GT_M);

    // gate MLP layer 1 (concat K over f1,f2)
    tgemm<0><<<gG1, 256, SM_TOTAL>>>(f1h, f2h, wth + OF_GW1T, gb1, h1, nullptr,
                                     NB, NH, ND, ND, nullptr, nullptr);
    ln_gelu_h<<<NB, NH / 4>>>(h1, gl1g, gl1b, h1h, NH);
    tgemm<0><<<gG2, 256, SM_TOTAL>>>(h1h, h1h, wth + OF_GW2T, gb2, h2, nullptr,
                                     NB, NH / 2, NH, 0, nullptr, nullptr);
    ln_gelu_h<<<NB, (NH / 2) / 4>>>(h2, gl2g, gl2b, h2h, NH / 2);
    // layer 3 + sigmoid gate combine -> gf (fp32) + gfh (half)
    tgemm<2><<<gD, 256, SM_TOTAL>>>(h2h, h2h, wth + OF_GW3T, gb3, gf, gfh,
                                    NB, ND, NH / 2, 0, f1, f2);
    // attention projections (fp32 outputs for elementwise attn)
    tgemm<0><<<gD, 256, SM_TOTAL>>>(gfh, gfh, wth + OF_QWT, qb, q, nullptr, NB, ND, ND, 0, nullptr, nullptr);
    tgemm<0><<<gD, 256, SM_TOTAL>>>(f1h, f1h, wth + OF_KWT, kb, k1, nullptr, NB, ND, ND, 0, nullptr, nullptr);
    tgemm<0><<<gD, 256, SM_TOTAL>>>(f2h, f2h, wth + OF_KWT, kb, k2, nullptr, NB, ND, ND, 0, nullptr, nullptr);
    tgemm<0><<<gD, 256, SM_TOTAL>>>(f1h, f1h, wth + OF_VWT, vb, v1, nullptr, NB, ND, ND, 0, nullptr, nullptr);
    tgemm<0><<<gD, 256, SM_TOTAL>>>(f2h, f2h, wth + OF_VWT, vb, v2, nullptr, NB, ND, ND, 0, nullptr, nullptr);
    attn_fused<<<NB, 256>>>(q, k1, k2, v1, v2, gf, f1, alng, alnb, ln1g, ln1b, res1);
    bn_count<<<1, 256>>>(ids);
    bn_stats<<<ND / 32, 256>>>(res1, ids);
    bn_apply<<<(NB * ND / 4) / 256, 256>>>(res1, ids, bng, bnb, nrm, nrmh);
    // FFN: mid kept half-only
    tgemm<1><<<g2D, 256, SM_TOTAL>>>(nrmh, nrmh, wth + OF_FW1T, fb1, nullptr, midh,
                                     NB, 2 * ND, ND, 0, nullptr, nullptr);
    tgemm<0><<<gD, 256, SM_TOTAL>>>(midh, midh, wth + OF_FW2T, fb2, q, nullptr,
                                    NB, ND, 2 * ND, 0, nullptr, nullptr);
    ln_residual<<<NB, 256>>>(q, nrm, ln2g, ln2b, out);
}

// round 6
// speedup vs baseline: 5.9145x; 1.2456x over previous
#include <cuda_runtime.h>
#include <cuda_fp16.h>
#include <math.h>
#include <stdint.h>

#define NB 8192
#define ND 2048
#define NH 512
#define NA 3
#define LNEPS 1e-5f
#define SQRT_D 45.25483399593904f

// ---------------- scratch (device globals; no allocation allowed) ----------
__device__ float g_h1[(size_t)NB * NH];
__device__ float g_h2[(size_t)NB * (NH / 2)];
__device__ float g_gf[(size_t)NB * ND];
__device__ float g_q[(size_t)NB * ND];       // gfM, later ffn2 out
__device__ float g_attn[(size_t)NB * ND];
__device__ float g_res1[(size_t)NB * ND];
__device__ float g_norm[(size_t)NB * ND];
__device__ float g_bnsum[NA * ND];
__device__ float g_bnsq[NA * ND];
__device__ int   g_cnt[NA];
__device__ float g_u[ND];
__device__ float g_w[ND];
__device__ float g_c[1];
__device__ float g_zero[4096];               // zero bias (zero-initialized)
// half activation buffers
__device__ __half g_f1h[(size_t)NB * ND];
__device__ __half g_f2h[(size_t)NB * ND];
__device__ __half g_h1h[(size_t)NB * NH];
__device__ __half g_h2h[(size_t)NB * (NH / 2)];
__device__ __half g_gfh[(size_t)NB * ND];
__device__ __half g_mixh[(size_t)NB * ND];
__device__ __half g_nrmh[(size_t)NB * ND];
__device__ __half g_midh[(size_t)NB * 2 * ND];   // FFN mid; also holds MT early
// half weights (transposed or raw)
__device__ __half g_wth[32112640];

#define OF_GW1T 0
#define OF_GW2T (OF_GW1T + 4096 * 512)
#define OF_GW3T (OF_GW2T + 512 * 256)
#define OF_QWH  (OF_GW3T + 256 * 2048)      /* qW raw half [2048,2048] */
#define OF_KWH  (OF_QWH + 2048 * 2048)      /* kW raw half [2048,2048] */
#define OF_VWT  (OF_KWH + 2048 * 2048)
#define OF_FW1T (OF_VWT + 2048 * 2048)
#define OF_FW2T (OF_FW1T + 2048 * 4096)

// ---------------- helpers ----------------
__device__ __forceinline__ float geluf(float x) {
    return 0.5f * x * (1.0f + erff(x * 0.70710678118654752f));
}
__device__ __forceinline__ uint32_t smem_u32(const void *p) {
    uint32_t a;
    asm("{ .reg .u64 t; cvta.to.shared.u64 t, %1; cvt.u32.u64 %0, t; }" : "=r"(a) : "l"(p));
    return a;
}
__device__ __forceinline__ uint32_t swz128(uint32_t off) {
    return off ^ ((off >> 3) & 0x70u);
}
__device__ __forceinline__ void cp16(uint32_t s, const void *g) {
    asm volatile("cp.async.cg.shared.global [%0], [%1], 16;" :: "r"(s), "l"(g));
}
__device__ __forceinline__ void cp_commit() { asm volatile("cp.async.commit_group;" ::: "memory"); }
template <int N> __device__ __forceinline__ void cp_wait() {
    asm volatile("cp.async.wait_group %0;" :: "n"(N) : "memory");
}
__device__ __forceinline__ void ldsm4(uint32_t *r, uint32_t addr) {
    asm volatile("ldmatrix.sync.aligned.m8n8.x4.shared.b16 {%0,%1,%2,%3}, [%4];"
                 : "=r"(r[0]), "=r"(r[1]), "=r"(r[2]), "=r"(r[3]) : "r"(addr));
}
__device__ __forceinline__ void mma16816(float *c, const uint32_t *a, const uint32_t *b) {
    asm volatile(
        "mma.sync.aligned.m16n8k16.row.col.f32.f16.f16.f32 "
        "{%0,%1,%2,%3}, {%4,%5,%6,%7}, {%8,%9}, {%0,%1,%2,%3};"
        : "+f"(c[0]), "+f"(c[1]), "+f"(c[2]), "+f"(c[3])
        : "r"(a[0]), "r"(a[1]), "r"(a[2]), "r"(a[3]), "r"(b[0]), "r"(b[1]));
}
__device__ __forceinline__ float dot4(float4 a, float4 b) {
    return a.x * b.x + a.y * b.y + a.z * b.z + a.w * b.w;
}

// two-value block reduction (sum); result broadcast to all threads
__device__ __forceinline__ void blockReduce2(float &a, float &b) {
    __shared__ float sa[32], sb[32];
#pragma unroll
    for (int o = 16; o; o >>= 1) {
        a += __shfl_xor_sync(0xFFFFFFFFu, a, o);
        b += __shfl_xor_sync(0xFFFFFFFFu, b, o);
    }
    const int lane = threadIdx.x & 31, w = threadIdx.x >> 5;
    const int nw = blockDim.x >> 5;
    if (nw > 1) {
        if (lane == 0) { sa[w] = a; sb[w] = b; }
        __syncthreads();
        a = (lane < nw) ? sa[lane] : 0.0f;
        b = (lane < nw) ? sb[lane] : 0.0f;
#pragma unroll
        for (int o = 16; o; o >>= 1) {
            a += __shfl_xor_sync(0xFFFFFFFFu, a, o);
            b += __shfl_xor_sync(0xFFFFFFFFu, b, o);
        }
        __syncthreads();
    }
}

// ---------------- weight transpose + f32->f16: in[K,N] -> out[N,K] --------
__global__ void transp(const float *__restrict__ in, __half *__restrict__ out,
                       int K, int N) {
    __shared__ float t[32][33];
    const int n0 = blockIdx.x * 32, k0 = blockIdx.y * 32;
#pragma unroll
    for (int i = threadIdx.y; i < 32; i += 8)
        t[i][threadIdx.x] = in[(size_t)(k0 + i) * N + n0 + threadIdx.x];
    __syncthreads();
#pragma unroll
    for (int i = threadIdx.y; i < 32; i += 8)
        out[(size_t)(n0 + i) * K + k0 + threadIdx.x] =
            __float2half_rn(t[threadIdx.x][i]);
}

// ---------------- f32 -> f16 convert ----------------
__global__ void cvt_half(const float4 *__restrict__ in, __half2 *__restrict__ out,
                         int n4) {
    int i = blockIdx.x * blockDim.x + threadIdx.x;
    if (i < n4) {
        float4 v = in[i];
        out[2 * i]     = __floats2half2_rn(v.x, v.y);
        out[2 * i + 1] = __floats2half2_rn(v.z, v.w);
    }
}

// ---------------- u = kW@qb, w = qW@kb, c = qb.kb ----------------
// grid 4097 blocks x 256 threads; block r<2048 -> u[r], <4096 -> w[r-2048], last -> c
__global__ __launch_bounds__(256) void vec_uwc(
    const float *__restrict__ qW, const float *__restrict__ kW,
    const float *__restrict__ qb, const float *__restrict__ kb,
    float *__restrict__ u, float *__restrict__ w, float *__restrict__ c)
{
    const int r = blockIdx.x, t = threadIdx.x;
    float s = 0.0f, dummy = 0.0f;
    if (r < ND) {
        const float4 *row = (const float4 *)(kW + (size_t)r * ND);
        const float4 *v = (const float4 *)qb;
#pragma unroll
        for (int p = 0; p < 2; p++) s += dot4(row[t + p * 256], v[t + p * 256]);
        blockReduce2(s, dummy);
        if (t == 0) u[r] = s;
    } else if (r < 2 * ND) {
        const float4 *row = (const float4 *)(qW + (size_t)(r - ND) * ND);
        const float4 *v = (const float4 *)kb;
#pragma unroll
        for (int p = 0; p < 2; p++) s += dot4(row[t + p * 256], v[t + p * 256]);
        blockReduce2(s, dummy);
        if (t == 0) w[r - ND] = s;
    } else {
        const float4 *a = (const float4 *)qb;
        const float4 *v = (const float4 *)kb;
#pragma unroll
        for (int p = 0; p < 2; p++) s += dot4(a[t + p * 256], v[t + p * 256]);
        blockReduce2(s, dummy);
        if (t == 0) *c = s;
    }
}

// ---------------- fp16 GEMM: C = concat_K(A1,A2) @ WT^T + bias -------------
#define GT_M 128
#define GT_N 128
#define GKH 64
#define SMA_SZ (GT_M * GKH * 2)
#define SMBUF  (2 * SMA_SZ)
#define SM_TOTAL (1024 + 2 * SMBUF)

template <int EPI>
__global__ __launch_bounds__(256) void tgemm(
    const __half *__restrict__ A1, const __half *__restrict__ A2,
    const __half *__restrict__ WT, const float *__restrict__ bias,
    float *__restrict__ C, __half *__restrict__ Ch,
    int M, int N, int K1, int K2,
    const float *__restrict__ e1, const float *__restrict__ e2)
{
    extern __shared__ char smem[];
    const uint32_t sb = smem_u32(smem);
    const uint32_t tile0 = (sb + 1023) & ~1023u;
    const int tid = threadIdx.x;
    const int wid = tid >> 5, lane = tid & 31;
    const size_t rowBase = (size_t)blockIdx.y * GT_M;
    const size_t colBase = (size_t)blockIdx.x * GT_N;
    const int K = K1 + K2;
    const int niter = K / GKH;

    const int warpM = (wid >> 1) * 32, warpN = (wid & 1) * 64;

    uint32_t aoff[4], boff[4];
    const __half *pA1[4], *pA2[4], *pB[4];
#pragma unroll
    for (int i = 0; i < 4; i++) {
        int c = tid + i * 256, r = c >> 3, k16 = c & 7;
        aoff[i] = swz128((uint32_t)(r * 128 + k16 * 16));
        pA1[i] = A1 + (rowBase + r) * (size_t)K1 + k16 * 8;
        pA2[i] = A2 + (rowBase + r) * (size_t)K2 + k16 * 8 - K1;
        boff[i] = SMA_SZ + aoff[i];
        pB[i] = WT + (colBase + r) * (size_t)K + k16 * 8;
    }

    uint32_t aBase[2];
    {
        uint32_t khiA = ((lane >> 4) & 1) * 16;
#pragma unroll
        for (int mt = 0; mt < 2; mt++) {
            int r = warpM + mt * 16 + (lane & 15);
            aBase[mt] = ((uint32_t)(r * 128 + ((r & 7) << 4))) ^ khiA;
        }
    }
    uint32_t bBase[4];
    {
        uint32_t khiB = ((lane >> 3) & 1) * 16;
#pragma unroll
        for (int p = 0; p < 4; p++) {
            int r = warpN + p * 16 + ((lane >> 4) & 1) * 8 + (lane & 7);
            bBase[p] = ((uint32_t)(r * 128 + ((r & 7) << 4))) ^ khiB;
        }
    }

    float acc[2][8][4];
#pragma unroll
    for (int mt = 0; mt < 2; mt++)
#pragma unroll
        for (int nt = 0; nt < 8; nt++)
#pragma unroll
            for (int j = 0; j < 4; j++) acc[mt][nt][j] = 0.0f;

#pragma unroll
    for (int i = 0; i < 4; i++) cp16(tile0 + aoff[i], pA1[i]);
#pragma unroll
    for (int i = 0; i < 4; i++) cp16(tile0 + boff[i], pB[i]);
    cp_commit();

    for (int it = 0; it < niter; ++it) {
        const int b = it & 1;
        if (it + 1 < niter) {
            const int nb = b ^ 1;
            const int kg = (it + 1) * GKH;
            const uint32_t tb = tile0 + nb * SMBUF;
            const bool s1 = kg < K1;
#pragma unroll
            for (int i = 0; i < 4; i++)
                cp16(tb + aoff[i], (s1 ? pA1[i] : pA2[i]) + kg);
#pragma unroll
            for (int i = 0; i < 4; i++) cp16(tb + boff[i], pB[i] + kg);
            cp_commit();
            cp_wait<1>();
        } else {
            cp_wait<0>();
        }
        __syncthreads();
        const uint32_t tA = tile0 + b * SMBUF;
        const uint32_t tB = tA + SMA_SZ;
#pragma unroll
        for (int k16 = 0; k16 < GKH / 16; ++k16) {
            const uint32_t kb2 = k16 * 32;
            uint32_t a[2][4];
            ldsm4(a[0], tA + (aBase[0] ^ kb2));
            ldsm4(a[1], tA + (aBase[1] ^ kb2));
            uint32_t bf[4][4];
#pragma unroll
            for (int p = 0; p < 4; p++) ldsm4(bf[p], tB + (bBase[p] ^ kb2));
#pragma unroll
            for (int mt = 0; mt < 2; mt++)
#pragma unroll
                for (int p = 0; p < 4; p++) {
                    mma16816(acc[mt][2 * p], a[mt], &bf[p][0]);
                    mma16816(acc[mt][2 * p + 1], a[mt], &bf[p][2]);
                }
        }
        __syncthreads();
    }

#pragma unroll
    for (int mt = 0; mt < 2; mt++) {
#pragma unroll
        for (int hf = 0; hf < 2; hf++) {
            const size_t m = rowBase + warpM + mt * 16 + (lane >> 2) + hf * 8;
            const size_t crow = m * (size_t)N;
#pragma unroll
            for (int nt = 0; nt < 8; nt++) {
                const size_t c0 = colBase + warpN + nt * 8 + (lane & 3) * 2;
                float v0 = acc[mt][nt][hf * 2 + 0] + bias[c0];
                float v1 = acc[mt][nt][hf * 2 + 1] + bias[c0 + 1];
                if (EPI == 1) { v0 = geluf(v0); v1 = geluf(v1); }
                if (EPI == 2) {
                    float s0 = 1.0f / (1.0f + expf(-v0));
                    float s1 = 1.0f / (1.0f + expf(-v1));
                    v0 = s0 * e1[crow + c0] + (1.0f - s0) * e2[crow + c0];
                    v1 = s1 * e1[crow + c0 + 1] + (1.0f - s1) * e2[crow + c0 + 1];
                }
                if (C) *(float2 *)(C + crow + c0) = make_float2(v0, v1);
                if (Ch) *(__half2 *)(Ch + crow + c0) = __floats2half2_rn(v0, v1);
            }
        }
    }
}

// ---------------- LN + exact GELU -> half out ----------------
__global__ void ln_gelu_h(const float *__restrict__ x, const float *__restrict__ g,
                          const float *__restrict__ b, __half *__restrict__ xh, int N)
{
    const size_t row = blockIdx.x;
    const float4 *xr = (const float4 *)(x + row * (size_t)N);
    const int t = threadIdx.x;
    float4 v = xr[t];
    float s = v.x + v.y + v.z + v.w;
    float sq = v.x * v.x + v.y * v.y + v.z * v.z + v.w * v.w;
    blockReduce2(s, sq);
    const float invN = 1.0f / (float)N;
    float mu = s * invN;
    float var = sq * invN - mu * mu;
    float rs = rsqrtf(var + LNEPS);
    float4 gv = ((const float4 *)g)[t];
    float4 bv = ((const float4 *)b)[t];
    v.x = geluf((v.x - mu) * rs * gv.x + bv.x);
    v.y = geluf((v.y - mu) * rs * gv.y + bv.y);
    v.z = geluf((v.z - mu) * rs * gv.z + bv.z);
    v.w = geluf((v.w - mu) * rs * gv.w + bv.w);
    __half2 *ho = (__half2 *)(xh + row * (size_t)N);
    ho[2 * t] = __floats2half2_rn(v.x, v.y);
    ho[2 * t + 1] = __floats2half2_rn(v.z, v.w);
}

// ---------------- scores + softmax + v-mix ----------------
// s1 = (gfM.f1 + f1.u + gf.w + c)/sqrtD ; s2 likewise with f2
// mix = w1*f1 + w2*f2 (half out)
__global__ __launch_bounds__(256) void scores_mix(
    const float *__restrict__ gfM, const float *__restrict__ f1,
    const float *__restrict__ f2, const float *__restrict__ gf,
    const float *__restrict__ uvec, const float *__restrict__ wvec,
    const float *__restrict__ cscal, __half *__restrict__ mixh)
{
    const size_t base4 = (size_t)blockIdx.x * (ND / 4);
    const int t = threadIdx.x;
    float4 f1v[2], f2v[2];
    float d1 = 0, d2 = 0, d3 = 0, d4 = 0, d5 = 0, dummy = 0;
#pragma unroll
    for (int p = 0; p < 2; p++) {
        int idx = t + p * 256;
        float4 m = ((const float4 *)gfM)[base4 + idx];
        f1v[p] = ((const float4 *)f1)[base4 + idx];
        f2v[p] = ((const float4 *)f2)[base4 + idx];
        float4 g = ((const float4 *)gf)[base4 + idx];
        float4 uu = ((const float4 *)uvec)[idx];
        float4 ww = ((const float4 *)wvec)[idx];
        d1 += dot4(m, f1v[p]);
        d2 += dot4(m, f2v[p]);
        d3 += dot4(f1v[p], uu);
        d4 += dot4(f2v[p], uu);
        d5 += dot4(g, ww);
    }
    blockReduce2(d1, d2);
    blockReduce2(d3, d4);
    blockReduce2(d5, dummy);
    const float c = *cscal;
    float s1 = (d1 + d3 + d5 + c) * (1.0f / SQRT_D);
    float s2 = (d2 + d4 + d5 + c) * (1.0f / SQRT_D);
    float mx = fmaxf(s1, s2);
    float e1v = expf(s1 - mx), e2v = expf(s2 - mx);
    float w1 = e1v / (e1v + e2v), w2 = 1.0f - w1;
    __half2 *ho = (__half2 *)(mixh) + base4 * 2;
#pragma unroll
    for (int p = 0; p < 2; p++) {
        int idx = t + p * 256;
        float4 a = f1v[p], b = f2v[p];
        float x0 = w1 * a.x + w2 * b.x;
        float x1 = w1 * a.y + w2 * b.y;
        float x2 = w1 * a.z + w2 * b.z;
        float x3 = w1 * a.w + w2 * b.w;
        ho[2 * idx] = __floats2half2_rn(x0, x1);
        ho[2 * idx + 1] = __floats2half2_rn(x2, x3);
    }
}

// ---------------- gated = LN(gf+attn); res1 = LN(gated+f1) ----------------
__global__ __launch_bounds__(256) void post_ln(
    const float *__restrict__ gf, const float *__restrict__ attn,
    const float *__restrict__ f1,
    const float *__restrict__ alng, const float *__restrict__ alnb,
    const float *__restrict__ ln1g, const float *__restrict__ ln1b,
    float *__restrict__ out)
{
    const size_t base4 = (size_t)blockIdx.x * (ND / 4);
    const int t = threadIdx.x;
    float4 xv[2];
    float s = 0.0f, sq = 0.0f;
#pragma unroll
    for (int p = 0; p < 2; p++) {
        int idx = t + p * 256;
        float4 g = ((const float4 *)gf)[base4 + idx];
        float4 a = ((const float4 *)attn)[base4 + idx];
        float4 x;
        x.x = g.x + a.x; x.y = g.y + a.y; x.z = g.z + a.z; x.w = g.w + a.w;
        xv[p] = x;
        s += x.x + x.y + x.z + x.w;
        sq += x.x * x.x + x.y * x.y + x.z * x.z + x.w * x.w;
    }
    blockReduce2(s, sq);
    const float invD = 1.0f / (float)ND;
    float mu = s * invD;
    float var = sq * invD - mu * mu;
    float rs = rsqrtf(var + LNEPS);

    float4 yv[2];
    float s3 = 0.0f, sq3 = 0.0f;
#pragma unroll
    for (int p = 0; p < 2; p++) {
        int idx = t + p * 256;
        float4 gv = ((const float4 *)alng)[idx];
        float4 bv = ((const float4 *)alnb)[idx];
        float4 fv = ((const float4 *)f1)[base4 + idx];
        float4 x = xv[p], y;
        y.x = (x.x - mu) * rs * gv.x + bv.x + fv.x;
        y.y = (x.y - mu) * rs * gv.y + bv.y + fv.y;
        y.z = (x.z - mu) * rs * gv.z + bv.z + fv.z;
        y.w = (x.w - mu) * rs * gv.w + bv.w + fv.w;
        yv[p] = y;
        s3 += y.x + y.y + y.z + y.w;
        sq3 += y.x * y.x + y.y * y.y + y.z * y.z + y.w * y.w;
    }
    blockReduce2(s3, sq3);
    float mu2 = s3 * invD;
    float var2 = sq3 * invD - mu2 * mu2;
    float rs2 = rsqrtf(var2 + LNEPS);
#pragma unroll
    for (int p = 0; p < 2; p++) {
        int idx = t + p * 256;
        float4 gv = ((const float4 *)ln1g)[idx];
        float4 bv = ((const float4 *)ln1b)[idx];
        float4 y = yv[p], o;
        o.x = (y.x - mu2) * rs2 * gv.x + bv.x;
        o.y = (y.y - mu2) * rs2 * gv.y + bv.y;
        o.z = (y.z - mu2) * rs2 * gv.z + bv.z;
        o.w = (y.w - mu2) * rs2 * gv.w + bv.w;
        ((float4 *)out)[base4 + idx] = o;
    }
}

// ---------------- aspect BN ----------------
__global__ void bn_count(const int *__restrict__ ids) {
    __shared__ int c[NA];
    if (threadIdx.x < NA) c[threadIdx.x] = 0;
    __syncthreads();
    for (int i = threadIdx.x; i < NB; i += blockDim.x) atomicAdd(&c[ids[i]], 1);
    __syncthreads();
    if (threadIdx.x < NA) g_cnt[threadIdx.x] = c[threadIdx.x];
}

__global__ __launch_bounds__(256) void bn_stats(const float *__restrict__ x,
                                                const int *__restrict__ ids)
{
    __shared__ float ssum[NA][32], ssq[NA][32];
    const int lane = threadIdx.x & 31;
    const int stripe = threadIdx.x >> 5;
    const int c = blockIdx.x * 32 + lane;
    if (stripe == 0) {
#pragma unroll
        for (int a = 0; a < NA; a++) { ssum[a][lane] = 0.0f; ssq[a][lane] = 0.0f; }
    }
    __syncthreads();
    float s0 = 0, s1 = 0, s2 = 0, q0 = 0, q1 = 0, q2 = 0;
#pragma unroll 4
    for (int r = stripe; r < NB; r += 8) {
        int a = ids[r];
        float v = x[(size_t)r * ND + c];
        float vv = v * v;
        if (a == 0) { s0 += v; q0 += vv; }
        else if (a == 1) { s1 += v; q1 += vv; }
        else { s2 += v; q2 += vv; }
    }
    atomicAdd(&ssum[0][lane], s0); atomicAdd(&ssq[0][lane], q0);
    atomicAdd(&ssum[1][lane], s1); atomicAdd(&ssq[1][lane], q1);
    atomicAdd(&ssum[2][lane], s2); atomicAdd(&ssq[2][lane], q2);
    __syncthreads();
    if (stripe < NA) {
        g_bnsum[stripe * ND + c] = ssum[stripe][lane];
        g_bnsq[stripe * ND + c] = ssq[stripe][lane];
    }
}

__global__ void bn_apply(const float *__restrict__ x, const int *__restrict__ ids,
                         const float *__restrict__ bng, const float *__restrict__ bnb,
                         float *__restrict__ out, __half *__restrict__ outh)
{
    const int i = blockIdx.x * blockDim.x + threadIdx.x;
    const int row = i >> 9;
    const int c4 = i & 511;
    const int a = ids[row];
    const int cnt = g_cnt[a];
    float4 v = ((const float4 *)x)[i];
    if (cnt > 1) {
        const float fc = (float)cnt;
        const int cb4 = (a * ND) / 4 + c4;
        float4 sm = ((const float4 *)g_bnsum)[cb4];
        float4 sc = ((const float4 *)g_bnsq)[cb4];
        float4 gv = ((const float4 *)bng)[cb4];
        float4 bv = ((const float4 *)bnb)[cb4];
        float m, vr;
        m = sm.x / fc; vr = sc.x / fc - m * m; v.x = (v.x - m) * rsqrtf(vr + LNEPS) * gv.x + bv.x;
        m = sm.y / fc; vr = sc.y / fc - m * m; v.y = (v.y - m) * rsqrtf(vr + LNEPS) * gv.y + bv.y;
        m = sm.z / fc; vr = sc.z / fc - m * m; v.z = (v.z - m) * rsqrtf(vr + LNEPS) * gv.z + bv.z;
        m = sm.w / fc; vr = sc.w / fc - m * m; v.w = (v.w - m) * rsqrtf(vr + LNEPS) * gv.w + bv.w;
    }
    ((float4 *)out)[i] = v;
    __half2 *ho = (__half2 *)outh;
    ho[2 * i] = __floats2half2_rn(v.x, v.y);
    ho[2 * i + 1] = __floats2half2_rn(v.z, v.w);
}

// ---------------- final LN(a + b) -> out ----------------
__global__ __launch_bounds__(256) void ln_residual(
    const float *__restrict__ x, const float *__restrict__ res,
    const float *__restrict__ g, const float *__restrict__ b,
    float *__restrict__ out)
{
    const size_t base4 = (size_t)blockIdx.x * (ND / 4);
    const int t = threadIdx.x;
    float4 v[2];
    float s = 0.0f, sq = 0.0f;
#pragma unroll
    for (int p = 0; p < 2; p++) {
        int idx = t + p * 256;
        float4 a = ((const float4 *)x)[base4 + idx];
        float4 r = ((const float4 *)res)[base4 + idx];
        a.x += r.x; a.y += r.y; a.z += r.z; a.w += r.w;
        v[p] = a;
        s += a.x + a.y + a.z + a.w;
        sq += a.x * a.x + a.y * a.y + a.z * a.z + a.w * a.w;
    }
    blockReduce2(s, sq);
    const float invD = 1.0f / (float)ND;
    float mu = s * invD;
    float var = sq * invD - mu * mu;
    float rs = rsqrtf(var + LNEPS);
#pragma unroll
    for (int p = 0; p < 2; p++) {
        int idx = t + p * 256;
        float4 gv = ((const float4 *)g)[idx];
        float4 bv = ((const float4 *)b)[idx];
        float4 a = v[p], o;
        o.x = (a.x - mu) * rs * gv.x + bv.x;
        o.y = (a.y - mu) * rs * gv.y + bv.y;
        o.z = (a.z - mu) * rs * gv.z + bv.z;
        o.w = (a.w - mu) * rs * gv.w + bv.w;
        ((float4 *)out)[base4 + idx] = o;
    }
}

// ---------------- launch ----------------
extern "C" void kernel_launch(void *const *d_in, const int *in_sizes, int n_in,
                              void *d_out, int out_size)
{
    const float *f1 = (const float *)d_in[0];
    const float *f2 = (const float *)d_in[1];
    const int *ids = (const int *)d_in[2];
    const float *gW1 = (const float *)d_in[3], *gb1 = (const float *)d_in[4];
    const float *gl1g = (const float *)d_in[5], *gl1b = (const float *)d_in[6];
    const float *gW2 = (const float *)d_in[7], *gb2 = (const float *)d_in[8];
    const float *gl2g = (const float *)d_in[9], *gl2b = (const float *)d_in[10];
    const float *gW3 = (const float *)d_in[11], *gb3 = (const float *)d_in[12];
    const float *qW = (const float *)d_in[13], *qb = (const float *)d_in[14];
    const float *kW = (const float *)d_in[15], *kb = (const float *)d_in[16];
    const float *vW = (const float *)d_in[17], *vb = (const float *)d_in[18];
    const float *alng = (const float *)d_in[19], *alnb = (const float *)d_in[20];
    const float *bng = (const float *)d_in[21], *bnb = (const float *)d_in[22];
    const float *ln1g = (const float *)d_in[23], *ln1b = (const float *)d_in[24];
    const float *fW1 = (const float *)d_in[25], *fb1 = (const float *)d_in[26];
    const float *fW2 = (const float *)d_in[27], *fb2 = (const float *)d_in[28];
    const float *ln2g = (const float *)d_in[29], *ln2b = (const float *)d_in[30];
    float *out = (float *)d_out;

    float *h1, *h2, *gf, *q, *attn, *res1, *nrm, *uv, *wv, *cv, *zb;
    __half *f1h, *f2h, *h1h, *h2h, *gfh, *mixh, *nrmh, *midh, *wth;
    cudaGetSymbolAddress((void **)&h1, g_h1);
    cudaGetSymbolAddress((void **)&h2, g_h2);
    cudaGetSymbolAddress((void **)&gf, g_gf);
    cudaGetSymbolAddress((void **)&q, g_q);
    cudaGetSymbolAddress((void **)&attn, g_attn);
    cudaGetSymbolAddress((void **)&res1, g_res1);
    cudaGetSymbolAddress((void **)&nrm, g_norm);
    cudaGetSymbolAddress((void **)&uv, g_u);
    cudaGetSymbolAddress((void **)&wv, g_w);
    cudaGetSymbolAddress((void **)&cv, g_c);
    cudaGetSymbolAddress((void **)&zb, g_zero);
    cudaGetSymbolAddress((void **)&f1h, g_f1h);
    cudaGetSymbolAddress((void **)&f2h, g_f2h);
    cudaGetSymbolAddress((void **)&h1h, g_h1h);
    cudaGetSymbolAddress((void **)&h2h, g_h2h);
    cudaGetSymbolAddress((void **)&gfh, g_gfh);
    cudaGetSymbolAddress((void **)&mixh, g_mixh);
    cudaGetSymbolAddress((void **)&nrmh, g_nrmh);
    cudaGetSymbolAddress((void **)&midh, g_midh);
    cudaGetSymbolAddress((void **)&wth, g_wth);

    cudaFuncSetAttribute(tgemm<0>, cudaFuncAttributeMaxDynamicSharedMemorySize, SM_TOTAL);
    cudaFuncSetAttribute(tgemm<1>, cudaFuncAttributeMaxDynamicSharedMemorySize, SM_TOTAL);
    cudaFuncSetAttribute(tgemm<2>, cudaFuncAttributeMaxDynamicSharedMemorySize, SM_TOTAL);

    // weight preprocessing
    dim3 tb(32, 8);
    transp<<<dim3(512 / 32, 4096 / 32), tb>>>(gW1, wth + OF_GW1T, 4096, 512);
    transp<<<dim3(256 / 32, 512 / 32), tb>>>(gW2, wth + OF_GW2T, 512, 256);
    transp<<<dim3(2048 / 32, 256 / 32), tb>>>(gW3, wth + OF_GW3T, 256, 2048);
    transp<<<dim3(2048 / 32, 2048 / 32), tb>>>(vW, wth + OF_VWT, 2048, 2048);
    transp<<<dim3(4096 / 32, 2048 / 32), tb>>>(fW1, wth + OF_FW1T, 2048, 4096);
    transp<<<dim3(2048 / 32, 4096 / 32), tb>>>(fW2, wth + OF_FW2T, 4096, 2048);
    // raw half conversions
    cvt_half<<<(NB * ND / 4) / 256, 256>>>((const float4 *)f1, (__half2 *)f1h, NB * ND / 4);
    cvt_half<<<(NB * ND / 4) / 256, 256>>>((const float4 *)f2, (__half2 *)f2h, NB * ND / 4);
    cvt_half<<<(ND * ND / 4) / 256, 256>>>((const float4 *)qW, (__half2 *)(wth + OF_QWH), ND * ND / 4);
    cvt_half<<<(ND * ND / 4) / 256, 256>>>((const float4 *)kW, (__half2 *)(wth + OF_KWH), ND * ND / 4);
    // u, w, c
    vec_uwc<<<2 * ND + 1, 256>>>(qW, kW, qb, kb, uv, wv, cv);
    // MT = kW @ qW^T (half out), stored in midh (free until FFN)
    tgemm<0><<<dim3(ND / GT_N, ND / GT_M), 256, SM_TOTAL>>>(
        wth + OF_KWH, wth + OF_KWH, wth + OF_QWH, zb, nullptr, midh,
        ND, ND, ND, 0, nullptr, nullptr);

    const dim3 gG1(NH / GT_N, NB / GT_M);
    const dim3 gG2((NH / 2) / GT_N, NB / GT_M);
    const dim3 gD(ND / GT_N, NB / GT_M);
    const dim3 g2D((2 * ND) / GT_N, NB / GT_M);

    // gate MLP
    tgemm<0><<<gG1, 256, SM_TOTAL>>>(f1h, f2h, wth + OF_GW1T, gb1, h1, nullptr,
                                     NB, NH, ND, ND, nullptr, nullptr);
    ln_gelu_h<<<NB, NH / 4>>>(h1, gl1g, gl1b, h1h, NH);
    tgemm<0><<<gG2, 256, SM_TOTAL>>>(h1h, h1h, wth + OF_GW2T, gb2, h2, nullptr,
                                     NB, NH / 2, NH, 0, nullptr, nullptr);
    ln_gelu_h<<<NB, (NH / 2) / 4>>>(h2, gl2g, gl2b, h2h, NH / 2);
    tgemm<2><<<gD, 256, SM_TOTAL>>>(h2h, h2h, wth + OF_GW3T, gb3, gf, gfh,
                                    NB, ND, NH / 2, 0, f1, f2);
    // gfM = gf @ M  (via MT half in midh)
    tgemm<0><<<gD, 256, SM_TOTAL>>>(gfh, gfh, midh, zb, q, nullptr,
                                    NB, ND, ND, 0, nullptr, nullptr);
    // scores + softmax + mix
    scores_mix<<<NB, 256>>>(q, f1, f2, gf, uv, wv, cv, mixh);
    // attn = mix @ vW + vb
    tgemm<0><<<gD, 256, SM_TOTAL>>>(mixh, mixh, wth + OF_VWT, vb, attn, nullptr,
                                    NB, ND, ND, 0, nullptr, nullptr);
    // gated/res1 LNs
    post_ln<<<NB, 256>>>(gf, attn, f1, alng, alnb, ln1g, ln1b, res1);
    // aspect BN
    bn_count<<<1, 256>>>(ids);
    bn_stats<<<ND / 32, 256>>>(res1, ids);
    bn_apply<<<(NB * ND / 4) / 256, 256>>>(res1, ids, bng, bnb, nrm, nrmh);
    // FFN
    tgemm<1><<<g2D, 256, SM_TOTAL>>>(nrmh, nrmh, wth + OF_FW1T, fb1, nullptr, midh,
                                     NB, 2 * ND, ND, 0, nullptr, nullptr);
    tgemm<0><<<gD, 256, SM_TOTAL>>>(midh, midh, wth + OF_FW2T, fb2, q, nullptr,
                                    NB, ND, 2 * ND, 0, nullptr, nullptr);
    ln_residual<<<NB, 256>>>(q, nrm, ln2g, ln2b, out);
}

// round 8
// speedup vs baseline: 6.1093x; 1.0329x over previous
#include <cuda_runtime.h>
#include <cuda_fp16.h>
#include <math.h>
#include <stdint.h>

#define NB 8192
#define ND 2048
#define NH 512
#define NA 3
#define LNEPS 1e-5f
#define SQRT_D 45.25483399593904f

// ---------------- scratch (device globals; no allocation allowed) ----------
__device__ float g_h1[(size_t)NB * NH];
__device__ float g_h2[(size_t)NB * (NH / 2)];
__device__ float g_gf[(size_t)NB * ND];
__device__ float g_q[(size_t)NB * ND];       // gfM, later ffn2 out
__device__ float g_attn[(size_t)NB * ND];
__device__ float g_res1[(size_t)NB * ND];
__device__ float g_norm[(size_t)NB * ND];
__device__ float g_bnsum[NA * ND];
__device__ float g_bnsq[NA * ND];
__device__ int   g_cnt[NA];
__device__ float g_u[ND];
__device__ float g_w[ND];
__device__ float g_c[1];
__device__ float g_zero[4096];               // zero bias (zero-initialized)
// half activation buffers
__device__ __half g_f1h[(size_t)NB * ND];
__device__ __half g_f2h[(size_t)NB * ND];
__device__ __half g_h1h[(size_t)NB * NH];
__device__ __half g_h2h[(size_t)NB * (NH / 2)];
__device__ __half g_gfh[(size_t)NB * ND];
__device__ __half g_mixh[(size_t)NB * ND];
__device__ __half g_nrmh[(size_t)NB * ND];
__device__ __half g_midh[(size_t)NB * 2 * ND];   // FFN mid; also holds MT early
// half weights (transposed or raw)
__device__ __half g_wth[32112640];

#define OF_GW1T 0
#define OF_GW2T (OF_GW1T + 4096 * 512)
#define OF_GW3T (OF_GW2T + 512 * 256)
#define OF_QWH  (OF_GW3T + 256 * 2048)      /* qW raw half [2048,2048] */
#define OF_KWH  (OF_QWH + 2048 * 2048)      /* kW raw half [2048,2048] */
#define OF_VWT  (OF_KWH + 2048 * 2048)
#define OF_FW1T (OF_VWT + 2048 * 2048)
#define OF_FW2T (OF_FW1T + 2048 * 4096)

// ---------------- helpers ----------------
__device__ __forceinline__ float geluf(float x) {
    return 0.5f * x * (1.0f + erff(x * 0.70710678118654752f));
}
__device__ __forceinline__ uint32_t smem_u32(const void *p) {
    uint32_t a;
    asm("{ .reg .u64 t; cvta.to.shared.u64 t, %1; cvt.u32.u64 %0, t; }" : "=r"(a) : "l"(p));
    return a;
}
__device__ __forceinline__ uint32_t swz128(uint32_t off) {
    return off ^ ((off >> 3) & 0x70u);
}
__device__ __forceinline__ void cp16(uint32_t s, const void *g) {
    asm volatile("cp.async.cg.shared.global [%0], [%1], 16;" :: "r"(s), "l"(g));
}
__device__ __forceinline__ void cp_commit() { asm volatile("cp.async.commit_group;" ::: "memory"); }
template <int N> __device__ __forceinline__ void cp_wait() {
    asm volatile("cp.async.wait_group %0;" :: "n"(N) : "memory");
}
__device__ __forceinline__ void ldsm4(uint32_t *r, uint32_t addr) {
    asm volatile("ldmatrix.sync.aligned.m8n8.x4.shared.b16 {%0,%1,%2,%3}, [%4];"
                 : "=r"(r[0]), "=r"(r[1]), "=r"(r[2]), "=r"(r[3]) : "r"(addr));
}
__device__ __forceinline__ void mma16816(float *c, const uint32_t *a, const uint32_t *b) {
    asm volatile(
        "mma.sync.aligned.m16n8k16.row.col.f32.f16.f16.f32 "
        "{%0,%1,%2,%3}, {%4,%5,%6,%7}, {%8,%9}, {%0,%1,%2,%3};"
        : "+f"(c[0]), "+f"(c[1]), "+f"(c[2]), "+f"(c[3])
        : "r"(a[0]), "r"(a[1]), "r"(a[2]), "r"(a[3]), "r"(b[0]), "r"(b[1]));
}
__device__ __forceinline__ float dot4(float4 a, float4 b) {
    return a.x * b.x + a.y * b.y + a.z * b.z + a.w * b.w;
}

// two-value block reduction (sum); result broadcast to all threads
__device__ __forceinline__ void blockReduce2(float &a, float &b) {
    __shared__ float sa[32], sb[32];
#pragma unroll
    for (int o = 16; o; o >>= 1) {
        a += __shfl_xor_sync(0xFFFFFFFFu, a, o);
        b += __shfl_xor_sync(0xFFFFFFFFu, b, o);
    }
    const int lane = threadIdx.x & 31, w = threadIdx.x >> 5;
    const int nw = blockDim.x >> 5;
    if (nw > 1) {
        if (lane == 0) { sa[w] = a; sb[w] = b; }
        __syncthreads();
        a = (lane < nw) ? sa[lane] : 0.0f;
        b = (lane < nw) ? sb[lane] : 0.0f;
#pragma unroll
        for (int o = 16; o; o >>= 1) {
            a += __shfl_xor_sync(0xFFFFFFFFu, a, o);
            b += __shfl_xor_sync(0xFFFFFFFFu, b, o);
        }
        __syncthreads();
    }
}

// ---------------- weight transpose + f32->f16: in[K,N] -> out[N,K] --------
__global__ void transp(const float *__restrict__ in, __half *__restrict__ out,
                       int K, int N) {
    __shared__ float t[32][33];
    const int n0 = blockIdx.x * 32, k0 = blockIdx.y * 32;
#pragma unroll
    for (int i = threadIdx.y; i < 32; i += 8)
        t[i][threadIdx.x] = in[(size_t)(k0 + i) * N + n0 + threadIdx.x];
    __syncthreads();
#pragma unroll
    for (int i = threadIdx.y; i < 32; i += 8)
        out[(size_t)(n0 + i) * K + k0 + threadIdx.x] =
            __float2half_rn(t[threadIdx.x][i]);
}

// ---------------- f32 -> f16 convert ----------------
__global__ void cvt_half(const float4 *__restrict__ in, __half2 *__restrict__ out,
                         int n4) {
    int i = blockIdx.x * blockDim.x + threadIdx.x;
    if (i < n4) {
        float4 v = in[i];
        out[2 * i]     = __floats2half2_rn(v.x, v.y);
        out[2 * i + 1] = __floats2half2_rn(v.z, v.w);
    }
}

// ---------------- u = kW@qb, w = qW@kb, c = qb.kb ----------------
__global__ __launch_bounds__(256) void vec_uwc(
    const float *__restrict__ qW, const float *__restrict__ kW,
    const float *__restrict__ qb, const float *__restrict__ kb,
    float *__restrict__ u, float *__restrict__ w, float *__restrict__ c)
{
    const int r = blockIdx.x, t = threadIdx.x;
    float s = 0.0f, dummy = 0.0f;
    if (r < ND) {
        const float4 *row = (const float4 *)(kW + (size_t)r * ND);
        const float4 *v = (const float4 *)qb;
#pragma unroll
        for (int p = 0; p < 2; p++) s += dot4(row[t + p * 256], v[t + p * 256]);
        blockReduce2(s, dummy);
        if (t == 0) u[r] = s;
    } else if (r < 2 * ND) {
        const float4 *row = (const float4 *)(qW + (size_t)(r - ND) * ND);
        const float4 *v = (const float4 *)kb;
#pragma unroll
        for (int p = 0; p < 2; p++) s += dot4(row[t + p * 256], v[t + p * 256]);
        blockReduce2(s, dummy);
        if (t == 0) w[r - ND] = s;
    } else {
        const float4 *a = (const float4 *)qb;
        const float4 *v = (const float4 *)kb;
#pragma unroll
        for (int p = 0; p < 2; p++) s += dot4(a[t + p * 256], v[t + p * 256]);
        blockReduce2(s, dummy);
        if (t == 0) *c = s;
    }
}

// ---------------- fp16 GEMM: C = concat_K(A1,A2) @ WT^T + bias -------------
// CTA tile 128x256, K chunk 64, 3-stage cp.async pipeline, warp tile 64x64.
#define GT_M 128
#define GT_N 256
#define GKH 64
#define SMA_SZ (GT_M * GKH * 2)         // 16384
#define SMB_SZ (GT_N * GKH * 2)         // 32768
#define STAGE_SZ (SMA_SZ + SMB_SZ)      // 49152
#define NSTAGE 3
#define SM_TOTAL (1024 + NSTAGE * STAGE_SZ)  // 148480

template <int EPI>
__global__ __launch_bounds__(256, 1) void tgemm(
    const __half *__restrict__ A1, const __half *__restrict__ A2,
    const __half *__restrict__ WT, const float *__restrict__ bias,
    float *__restrict__ C, __half *__restrict__ Ch,
    int M, int N, int K1, int K2,
    const float *__restrict__ e1, const float *__restrict__ e2)
{
    extern __shared__ char smem[];
    const uint32_t sb = smem_u32(smem);
    const uint32_t tile0 = (sb + 1023) & ~1023u;
    const int tid = threadIdx.x;
    const int wid = tid >> 5, lane = tid & 31;
    const size_t rowBase = (size_t)blockIdx.y * GT_M;
    const size_t colBase = (size_t)blockIdx.x * GT_N;
    const int K = K1 + K2;
    const int niter = K / GKH;

    const int warpM = (wid >> 2) * 64, warpN = (wid & 3) * 64;

    // cp.async chunk mapping: A 4 chunks/thread, B 8 chunks/thread
    uint32_t aoff[4], boff[8];
    const __half *pA1[4], *pA2[4], *pB[8];
#pragma unroll
    for (int i = 0; i < 4; i++) {
        int c = tid + i * 256, r = c >> 3, k16 = c & 7;
        aoff[i] = swz128((uint32_t)(r * 128 + k16 * 16));
        pA1[i] = A1 + (rowBase + r) * (size_t)K1 + k16 * 8;
        pA2[i] = A2 + (rowBase + r) * (size_t)K2 + k16 * 8 - K1;
    }
#pragma unroll
    for (int i = 0; i < 8; i++) {
        int c = tid + i * 256, r = c >> 3, k16 = c & 7;
        boff[i] = SMA_SZ + swz128((uint32_t)(r * 128 + k16 * 16));
        pB[i] = WT + (colBase + r) * (size_t)K + k16 * 8;
    }

    // ldmatrix per-lane base addresses (swizzle pre-applied, column 0)
    uint32_t aBase[4];
    {
        uint32_t khiA = ((lane >> 4) & 1) * 16;
#pragma unroll
        for (int mt = 0; mt < 4; mt++) {
            int r = warpM + mt * 16 + (lane & 15);
            aBase[mt] = ((uint32_t)(r * 128 + ((r & 7) << 4))) ^ khiA;
        }
    }
    uint32_t bBase[4];
    {
        uint32_t khiB = ((lane >> 3) & 1) * 16;
#pragma unroll
        for (int p = 0; p < 4; p++) {
            int r = warpN + p * 16 + ((lane >> 4) & 1) * 8 + (lane & 7);
            bBase[p] = ((uint32_t)(r * 128 + ((r & 7) << 4))) ^ khiB;
        }
    }

    float acc[4][8][4];
#pragma unroll
    for (int mt = 0; mt < 4; mt++)
#pragma unroll
        for (int nt = 0; nt < 8; nt++)
#pragma unroll
            for (int j = 0; j < 4; j++) acc[mt][nt][j] = 0.0f;

    // stage loader
    auto load_stage = [&](int st, int kg) {
        const uint32_t tb = tile0 + st * STAGE_SZ;
        const bool s1 = kg < K1;
#pragma unroll
        for (int i = 0; i < 4; i++)
            cp16(tb + aoff[i], (s1 ? pA1[i] : pA2[i]) + kg);
#pragma unroll
        for (int i = 0; i < 8; i++) cp16(tb + boff[i], pB[i] + kg);
    };

    // prologue: stages 0,1
    load_stage(0, 0); cp_commit();
    if (niter > 1) load_stage(1, GKH);
    cp_commit();

    for (int it = 0; it < niter; ++it) {
        cp_wait<1>();
        __syncthreads();
        if (it + 2 < niter) load_stage((it + 2) % NSTAGE, (it + 2) * GKH);
        cp_commit();
        const uint32_t tA = tile0 + (it % NSTAGE) * STAGE_SZ;
        const uint32_t tB = tA + SMA_SZ;
#pragma unroll
        for (int k16 = 0; k16 < GKH / 16; ++k16) {
            const uint32_t kb2 = k16 * 32;
            uint32_t a[4][4];
#pragma unroll
            for (int mt = 0; mt < 4; mt++) ldsm4(a[mt], tA + (aBase[mt] ^ kb2));
            uint32_t bf[4][4];
#pragma unroll
            for (int p = 0; p < 4; p++) ldsm4(bf[p], tB + (bBase[p] ^ kb2));
#pragma unroll
            for (int mt = 0; mt < 4; mt++)
#pragma unroll
                for (int p = 0; p < 4; p++) {
                    mma16816(acc[mt][2 * p], a[mt], &bf[p][0]);
                    mma16816(acc[mt][2 * p + 1], a[mt], &bf[p][2]);
                }
        }
    }

    // epilogue
#pragma unroll
    for (int mt = 0; mt < 4; mt++) {
#pragma unroll
        for (int hf = 0; hf < 2; hf++) {
            const size_t m = rowBase + warpM + mt * 16 + (lane >> 2) + hf * 8;
            const size_t crow = m * (size_t)N;
#pragma unroll
            for (int nt = 0; nt < 8; nt++) {
                const size_t c0 = colBase + warpN + nt * 8 + (lane & 3) * 2;
                float v0 = acc[mt][nt][hf * 2 + 0] + bias[c0];
                float v1 = acc[mt][nt][hf * 2 + 1] + bias[c0 + 1];
                if (EPI == 1) { v0 = geluf(v0); v1 = geluf(v1); }
                if (EPI == 2) {
                    float s0 = 1.0f / (1.0f + expf(-v0));
                    float s1 = 1.0f / (1.0f + expf(-v1));
                    v0 = s0 * e1[crow + c0] + (1.0f - s0) * e2[crow + c0];
                    v1 = s1 * e1[crow + c0 + 1] + (1.0f - s1) * e2[crow + c0 + 1];
                }
                if (C) *(float2 *)(C + crow + c0) = make_float2(v0, v1);
                if (Ch) *(__half2 *)(Ch + crow + c0) = __floats2half2_rn(v0, v1);
            }
        }
    }
}

// ---------------- LN + exact GELU -> half out ----------------
__global__ void ln_gelu_h(const float *__restrict__ x, const float *__restrict__ g,
                          const float *__restrict__ b, __half *__restrict__ xh, int N)
{
    const size_t row = blockIdx.x;
    const float4 *xr = (const float4 *)(x + row * (size_t)N);
    const int t = threadIdx.x;
    float4 v = xr[t];
    float s = v.x + v.y + v.z + v.w;
    float sq = v.x * v.x + v.y * v.y + v.z * v.z + v.w * v.w;
    blockReduce2(s, sq);
    const float invN = 1.0f / (float)N;
    float mu = s * invN;
    float var = sq * invN - mu * mu;
    float rs = rsqrtf(var + LNEPS);
    float4 gv = ((const float4 *)g)[t];
    float4 bv = ((const float4 *)b)[t];
    v.x = geluf((v.x - mu) * rs * gv.x + bv.x);
    v.y = geluf((v.y - mu) * rs * gv.y + bv.y);
    v.z = geluf((v.z - mu) * rs * gv.z + bv.z);
    v.w = geluf((v.w - mu) * rs * gv.w + bv.w);
    __half2 *ho = (__half2 *)(xh + row * (size_t)N);
    ho[2 * t] = __floats2half2_rn(v.x, v.y);
    ho[2 * t + 1] = __floats2half2_rn(v.z, v.w);
}

// ---------------- scores + softmax + v-mix ----------------
__global__ __launch_bounds__(256) void scores_mix(
    const float *__restrict__ gfM, const float *__restrict__ f1,
    const float *__restrict__ f2, const float *__restrict__ gf,
    const float *__restrict__ uvec, const float *__restrict__ wvec,
    const float *__restrict__ cscal, __half *__restrict__ mixh)
{
    const size_t base4 = (size_t)blockIdx.x * (ND / 4);
    const int t = threadIdx.x;
    float4 f1v[2], f2v[2];
    float d1 = 0, d2 = 0, d3 = 0, d4 = 0, d5 = 0, dummy = 0;
#pragma unroll
    for (int p = 0; p < 2; p++) {
        int idx = t + p * 256;
        float4 m = ((const float4 *)gfM)[base4 + idx];
        f1v[p] = ((const float4 *)f1)[base4 + idx];
        f2v[p] = ((const float4 *)f2)[base4 + idx];
        float4 g = ((const float4 *)gf)[base4 + idx];
        float4 uu = ((const float4 *)uvec)[idx];
        float4 ww = ((const float4 *)wvec)[idx];
        d1 += dot4(m, f1v[p]);
        d2 += dot4(m, f2v[p]);
        d3 += dot4(f1v[p], uu);
        d4 += dot4(f2v[p], uu);
        d5 += dot4(g, ww);
    }
    blockReduce2(d1, d2);
    blockReduce2(d3, d4);
    blockReduce2(d5, dummy);
    const float c = *cscal;
    float s1 = (d1 + d3 + d5 + c) * (1.0f / SQRT_D);
    float s2 = (d2 + d4 + d5 + c) * (1.0f / SQRT_D);
    float mx = fmaxf(s1, s2);
    float e1v = expf(s1 - mx), e2v = expf(s2 - mx);
    float w1 = e1v / (e1v + e2v), w2 = 1.0f - w1;
    __half2 *ho = (__half2 *)(mixh) + base4 * 2;
#pragma unroll
    for (int p = 0; p < 2; p++) {
        int idx = t + p * 256;
        float4 a = f1v[p], b = f2v[p];
        ho[2 * idx] = __floats2half2_rn(w1 * a.x + w2 * b.x, w1 * a.y + w2 * b.y);
        ho[2 * idx + 1] = __floats2half2_rn(w1 * a.z + w2 * b.z, w1 * a.w + w2 * b.w);
    }
}

// ---------------- gated = LN(gf+attn); res1 = LN(gated+f1) ----------------
__global__ __launch_bounds__(256) void post_ln(
    const float *__restrict__ gf, const float *__restrict__ attn,
    const float *__restrict__ f1,
    const float *__restrict__ alng, const float *__restrict__ alnb,
    const float *__restrict__ ln1g, const float *__restrict__ ln1b,
    float *__restrict__ out)
{
    const size_t base4 = (size_t)blockIdx.x * (ND / 4);
    const int t = threadIdx.x;
    float4 xv[2];
    float s = 0.0f, sq = 0.0f;
#pragma unroll
    for (int p = 0; p < 2; p++) {
        int idx = t + p * 256;
        float4 g = ((const float4 *)gf)[base4 + idx];
        float4 a = ((const float4 *)attn)[base4 + idx];
        float4 x;
        x.x = g.x + a.x; x.y = g.y + a.y; x.z = g.z + a.z; x.w = g.w + a.w;
        xv[p] = x;
        s += x.x + x.y + x.z + x.w;
        sq += x.x * x.x + x.y * x.y + x.z * x.z + x.w * x.w;
    }
    blockReduce2(s, sq);
    const float invD = 1.0f / (float)ND;
    float mu = s * invD;
    float var = sq * invD - mu * mu;
    float rs = rsqrtf(var + LNEPS);

    float4 yv[2];
    float s3 = 0.0f, sq3 = 0.0f;
#pragma unroll
    for (int p = 0; p < 2; p++) {
        int idx = t + p * 256;
        float4 gv = ((const float4 *)alng)[idx];
        float4 bv = ((const float4 *)alnb)[idx];
        float4 fv = ((const float4 *)f1)[base4 + idx];
        float4 x = xv[p], y;
        y.x = (x.x - mu) * rs * gv.x + bv.x + fv.x;
        y.y = (x.y - mu) * rs * gv.y + bv.y + fv.y;
        y.z = (x.z - mu) * rs * gv.z + bv.z + fv.z;
        y.w = (x.w - mu) * rs * gv.w + bv.w + fv.w;
        yv[p] = y;
        s3 += y.x + y.y + y.z + y.w;
        sq3 += y.x * y.x + y.y * y.y + y.z * y.z + y.w * y.w;
    }
    blockReduce2(s3, sq3);
    float mu2 = s3 * invD;
    float var2 = sq3 * invD - mu2 * mu2;
    float rs2 = rsqrtf(var2 + LNEPS);
#pragma unroll
    for (int p = 0; p < 2; p++) {
        int idx = t + p * 256;
        float4 gv = ((const float4 *)ln1g)[idx];
        float4 bv = ((const float4 *)ln1b)[idx];
        float4 y = yv[p], o;
        o.x = (y.x - mu2) * rs2 * gv.x + bv.x;
        o.y = (y.y - mu2) * rs2 * gv.y + bv.y;
        o.z = (y.z - mu2) * rs2 * gv.z + bv.z;
        o.w = (y.w - mu2) * rs2 * gv.w + bv.w;
        ((float4 *)out)[base4 + idx] = o;
    }
}

// ---------------- aspect BN ----------------
__global__ void bn_count(const int *__restrict__ ids) {
    __shared__ int c[NA];
    if (threadIdx.x < NA) c[threadIdx.x] = 0;
    __syncthreads();
    for (int i = threadIdx.x; i < NB; i += blockDim.x) atomicAdd(&c[ids[i]], 1);
    __syncthreads();
    if (threadIdx.x < NA) g_cnt[threadIdx.x] = c[threadIdx.x];
}

__global__ __launch_bounds__(256) void bn_stats(const float *__restrict__ x,
                                                const int *__restrict__ ids)
{
    __shared__ float ssum[NA][32], ssq[NA][32];
    const int lane = threadIdx.x & 31;
    const int stripe = threadIdx.x >> 5;
    const int c = blockIdx.x * 32 + lane;
    if (stripe == 0) {
#pragma unroll
        for (int a = 0; a < NA; a++) { ssum[a][lane] = 0.0f; ssq[a][lane] = 0.0f; }
    }
    __syncthreads();
    float s0 = 0, s1 = 0, s2 = 0, q0 = 0, q1 = 0, q2 = 0;
#pragma unroll 4
    for (int r = stripe; r < NB; r += 8) {
        int a = ids[r];
        float v = x[(size_t)r * ND + c];
        float vv = v * v;
        if (a == 0) { s0 += v; q0 += vv; }
        else if (a == 1) { s1 += v; q1 += vv; }
        else { s2 += v; q2 += vv; }
    }
    atomicAdd(&ssum[0][lane], s0); atomicAdd(&ssq[0][lane], q0);
    atomicAdd(&ssum[1][lane], s1); atomicAdd(&ssq[1][lane], q1);
    atomicAdd(&ssum[2][lane], s2); atomicAdd(&ssq[2][lane], q2);
    __syncthreads();
    if (stripe < NA) {
        g_bnsum[stripe * ND + c] = ssum[stripe][lane];
        g_bnsq[stripe * ND + c] = ssq[stripe][lane];
    }
}

__global__ void bn_apply(const float *__restrict__ x, const int *__restrict__ ids,
                         const float *__restrict__ bng, const float *__restrict__ bnb,
                         float *__restrict__ out, __half *__restrict__ outh)
{
    const int i = blockIdx.x * blockDim.x + threadIdx.x;
    const int row = i >> 9;
    const int c4 = i & 511;
    const int a = ids[row];
    const int cnt = g_cnt[a];
    float4 v = ((const float4 *)x)[i];
    if (cnt > 1) {
        const float fc = (float)cnt;
        const int cb4 = (a * ND) / 4 + c4;
        float4 sm = ((const float4 *)g_bnsum)[cb4];
        float4 sc = ((const float4 *)g_bnsq)[cb4];
        float4 gv = ((const float4 *)bng)[cb4];
        float4 bv = ((const float4 *)bnb)[cb4];
        float m, vr;
        m = sm.x / fc; vr = sc.x / fc - m * m; v.x = (v.x - m) * rsqrtf(vr + LNEPS) * gv.x + bv.x;
        m = sm.y / fc; vr = sc.y / fc - m * m; v.y = (v.y - m) * rsqrtf(vr + LNEPS) * gv.y + bv.y;
        m = sm.z / fc; vr = sc.z / fc - m * m; v.z = (v.z - m) * rsqrtf(vr + LNEPS) * gv.z + bv.z;
        m = sm.w / fc; vr = sc.w / fc - m * m; v.w = (v.w - m) * rsqrtf(vr + LNEPS) * gv.w + bv.w;
    }
    ((float4 *)out)[i] = v;
    __half2 *ho = (__half2 *)outh;
    ho[2 * i] = __floats2half2_rn(v.x, v.y);
    ho[2 * i + 1] = __floats2half2_rn(v.z, v.w);
}

// ---------------- final LN(a + b) -> out ----------------
__global__ __launch_bounds__(256) void ln_residual(
    const float *__restrict__ x, const float *__restrict__ res,
    const float *__restrict__ g, const float *__restrict__ b,
    float *__restrict__ out)
{
    const size_t base4 = (size_t)blockIdx.x * (ND / 4);
    const int t = threadIdx.x;
    float4 v[2];
    float s = 0.0f, sq = 0.0f;
#pragma unroll
    for (int p = 0; p < 2; p++) {
        int idx = t + p * 256;
        float4 a = ((const float4 *)x)[base4 + idx];
        float4 r = ((const float4 *)res)[base4 + idx];
        a.x += r.x; a.y += r.y; a.z += r.z; a.w += r.w;
        v[p] = a;
        s += a.x + a.y + a.z + a.w;
        sq += a.x * a.x + a.y * a.y + a.z * a.z + a.w * a.w;
    }
    blockReduce2(s, sq);
    const float invD = 1.0f / (float)ND;
    float mu = s * invD;
    float var = sq * invD - mu * mu;
    float rs = rsqrtf(var + LNEPS);
#pragma unroll
    for (int p = 0; p < 2; p++) {
        int idx = t + p * 256;
        float4 gv = ((const float4 *)g)[idx];
        float4 bv = ((const float4 *)b)[idx];
        float4 a = v[p], o;
        o.x = (a.x - mu) * rs * gv.x + bv.x;
        o.y = (a.y - mu) * rs * gv.y + bv.y;
        o.z = (a.z - mu) * rs * gv.z + bv.z;
        o.w = (a.w - mu) * rs * gv.w + bv.w;
        ((float4 *)out)[base4 + idx] = o;
    }
}

// ---------------- launch ----------------
extern "C" void kernel_launch(void *const *d_in, const int *in_sizes, int n_in,
                              void *d_out, int out_size)
{
    const float *f1 = (const float *)d_in[0];
    const float *f2 = (const float *)d_in[1];
    const int *ids = (const int *)d_in[2];
    const float *gW1 = (const float *)d_in[3], *gb1 = (const float *)d_in[4];
    const float *gl1g = (const float *)d_in[5], *gl1b = (const float *)d_in[6];
    const float *gW2 = (const float *)d_in[7], *gb2 = (const float *)d_in[8];
    const float *gl2g = (const float *)d_in[9], *gl2b = (const float *)d_in[10];
    const float *gW3 = (const float *)d_in[11], *gb3 = (const float *)d_in[12];
    const float *qW = (const float *)d_in[13], *qb = (const float *)d_in[14];
    const float *kW = (const float *)d_in[15], *kb = (const float *)d_in[16];
    const float *vW = (const float *)d_in[17], *vb = (const float *)d_in[18];
    const float *alng = (const float *)d_in[19], *alnb = (const float *)d_in[20];
    const float *bng = (const float *)d_in[21], *bnb = (const float *)d_in[22];
    const float *ln1g = (const float *)d_in[23], *ln1b = (const float *)d_in[24];
    const float *fW1 = (const float *)d_in[25], *fb1 = (const float *)d_in[26];
    const float *fW2 = (const float *)d_in[27], *fb2 = (const float *)d_in[28];
    const float *ln2g = (const float *)d_in[29], *ln2b = (const float *)d_in[30];
    float *out = (float *)d_out;

    float *h1, *h2, *gf, *q, *attn, *res1, *nrm, *uv, *wv, *cv, *zb;
    __half *f1h, *f2h, *h1h, *h2h, *gfh, *mixh, *nrmh, *midh, *wth;
    cudaGetSymbolAddress((void **)&h1, g_h1);
    cudaGetSymbolAddress((void **)&h2, g_h2);
    cudaGetSymbolAddress((void **)&gf, g_gf);
    cudaGetSymbolAddress((void **)&q, g_q);
    cudaGetSymbolAddress((void **)&attn, g_attn);
    cudaGetSymbolAddress((void **)&res1, g_res1);
    cudaGetSymbolAddress((void **)&nrm, g_norm);
    cudaGetSymbolAddress((void **)&uv, g_u);
    cudaGetSymbolAddress((void **)&wv, g_w);
    cudaGetSymbolAddress((void **)&cv, g_c);
    cudaGetSymbolAddress((void **)&zb, g_zero);
    cudaGetSymbolAddress((void **)&f1h, g_f1h);
    cudaGetSymbolAddress((void **)&f2h, g_f2h);
    cudaGetSymbolAddress((void **)&h1h, g_h1h);
    cudaGetSymbolAddress((void **)&h2h, g_h2h);
    cudaGetSymbolAddress((void **)&gfh, g_gfh);
    cudaGetSymbolAddress((void **)&mixh, g_mixh);
    cudaGetSymbolAddress((void **)&nrmh, g_nrmh);
    cudaGetSymbolAddress((void **)&midh, g_midh);
    cudaGetSymbolAddress((void **)&wth, g_wth);

    cudaFuncSetAttribute(tgemm<0>, cudaFuncAttributeMaxDynamicSharedMemorySize, SM_TOTAL);
    cudaFuncSetAttribute(tgemm<1>, cudaFuncAttributeMaxDynamicSharedMemorySize, SM_TOTAL);
    cudaFuncSetAttribute(tgemm<2>, cudaFuncAttributeMaxDynamicSharedMemorySize, SM_TOTAL);

    // weight preprocessing
    dim3 tb(32, 8);
    transp<<<dim3(512 / 32, 4096 / 32), tb>>>(gW1, wth + OF_GW1T, 4096, 512);
    transp<<<dim3(256 / 32, 512 / 32), tb>>>(gW2, wth + OF_GW2T, 512, 256);
    transp<<<dim3(2048 / 32, 256 / 32), tb>>>(gW3, wth + OF_GW3T, 256, 2048);
    transp<<<dim3(2048 / 32, 2048 / 32), tb>>>(vW, wth + OF_VWT, 2048, 2048);
    transp<<<dim3(4096 / 32, 2048 / 32), tb>>>(fW1, wth + OF_FW1T, 2048, 4096);
    transp<<<dim3(2048 / 32, 4096 / 32), tb>>>(fW2, wth + OF_FW2T, 4096, 2048);
    cvt_half<<<(NB * ND / 4) / 256, 256>>>((const float4 *)f1, (__half2 *)f1h, NB * ND / 4);
    cvt_half<<<(NB * ND / 4) / 256, 256>>>((const float4 *)f2, (__half2 *)f2h, NB * ND / 4);
    cvt_half<<<(ND * ND / 4) / 256, 256>>>((const float4 *)qW, (__half2 *)(wth + OF_QWH), ND * ND / 4);
    cvt_half<<<(ND * ND / 4) / 256, 256>>>((const float4 *)kW, (__half2 *)(wth + OF_KWH), ND * ND / 4);
    vec_uwc<<<2 * ND + 1, 256>>>(qW, kW, qb, kb, uv, wv, cv);
    // MT = kW @ qW^T (half out), stored in midh (free until FFN)
    tgemm<0><<<dim3(ND / GT_N, ND / GT_M), 256, SM_TOTAL>>>(
        wth + OF_KWH, wth + OF_KWH, wth + OF_QWH, zb, nullptr, midh,
        ND, ND, ND, 0, nullptr, nullptr);

    const dim3 gG1(NH / GT_N, NB / GT_M);        // 2 x 64
    const dim3 gG2((NH / 2) / GT_N, NB / GT_M);  // 1 x 64
    const dim3 gD(ND / GT_N, NB / GT_M);         // 8 x 64
    const dim3 g2D((2 * ND) / GT_N, NB / GT_M);  // 16 x 64

    // gate MLP
    tgemm<0><<<gG1, 256, SM_TOTAL>>>(f1h, f2h, wth + OF_GW1T, gb1, h1, nullptr,
                                     NB, NH, ND, ND, nullptr, nullptr);
    ln_gelu_h<<<NB, NH / 4>>>(h1, gl1g, gl1b, h1h, NH);
    tgemm<0><<<gG2, 256, SM_TOTAL>>>(h1h, h1h, wth + OF_GW2T, gb2, h2, nullptr,
                                     NB, NH / 2, NH, 0, nullptr, nullptr);
    ln_gelu_h<<<NB, (NH / 2) / 4>>>(h2, gl2g, gl2b, h2h, NH / 2);
    tgemm<2><<<gD, 256, SM_TOTAL>>>(h2h, h2h, wth + OF_GW3T, gb3, gf, gfh,
                                    NB, ND, NH / 2, 0, f1, f2);
    // gfM = gf @ M  (via MT half in midh)
    tgemm<0><<<gD, 256, SM_TOTAL>>>(gfh, gfh, midh, zb, q, nullptr,
                                    NB, ND, ND, 0, nullptr, nullptr);
    scores_mix<<<NB, 256>>>(q, f1, f2, gf, uv, wv, cv, mixh);
    // attn = mix @ vW + vb
    tgemm<0><<<gD, 256, SM_TOTAL>>>(mixh, mixh, wth + OF_VWT, vb, attn, nullptr,
                                    NB, ND, ND, 0, nullptr, nullptr);
    post_ln<<<NB, 256>>>(gf, attn, f1, alng, alnb, ln1g, ln1b, res1);
    bn_count<<<1, 256>>>(ids);
    bn_stats<<<ND / 32, 256>>>(res1, ids);
    bn_apply<<<(NB * ND / 4) / 256, 256>>>(res1, ids, bng, bnb, nrm, nrmh);
    // FFN
    tgemm<1><<<g2D, 256, SM_TOTAL>>>(nrmh, nrmh, wth + OF_FW1T, fb1, nullptr, midh,
                                     NB, 2 * ND, ND, 0, nullptr, nullptr);
    tgemm<0><<<gD, 256, SM_TOTAL>>>(midh, midh, wth + OF_FW2T, fb2, q, nullptr,
                                    NB, ND, 2 * ND, 0, nullptr, nullptr);
    ln_residual<<<NB, 256>>>(q, nrm, ln2g, ln2b, out);
}

// round 9
// speedup vs baseline: 6.2209x; 1.0183x over previous
#include <cuda_runtime.h>
#include <cuda_fp16.h>
#include <math.h>
#include <stdint.h>

#define NB 8192
#define ND 2048
#define NH 512
#define NA 3
#define LNEPS 1e-5f
#define SQRT_D 45.25483399593904f

// ---------------- scratch (device globals; no allocation allowed) ----------
__device__ float g_h1[(size_t)NB * NH];
__device__ float g_h2[(size_t)NB * (NH / 2)];
__device__ float g_gf[(size_t)NB * ND];
__device__ float g_q[(size_t)NB * ND];       // gfM f32 unused now; ffn2 out
__device__ float g_attn[(size_t)NB * ND];
__device__ float g_res1[(size_t)NB * ND];
__device__ float g_bnsum[NA * ND];
__device__ float g_bnsq[NA * ND];
__device__ int   g_cnt[NA];
__device__ float g_u[ND];
__device__ float g_w[ND];
__device__ float g_c[1];
__device__ float g_zero[4096];               // zero bias (zero-initialized)
// half activation buffers
__device__ __half g_f1h[(size_t)NB * ND];
__device__ __half g_f2h[(size_t)NB * ND];
__device__ __half g_h1h[(size_t)NB * NH];
__device__ __half g_h2h[(size_t)NB * (NH / 2)];
__device__ __half g_gfh[(size_t)NB * ND];
__device__ __half g_mixh[(size_t)NB * ND];   // gfM half, overwritten in-place by mix
__device__ __half g_nrmh[(size_t)NB * ND];
__device__ __half g_midh[(size_t)NB * 2 * ND];   // FFN mid; also holds MT early
// half weights (transposed or raw)
__device__ __half g_wth[32112640];

#define OF_GW1T 0
#define OF_GW2T (OF_GW1T + 4096 * 512)
#define OF_GW3T (OF_GW2T + 512 * 256)
#define OF_QWH  (OF_GW3T + 256 * 2048)      /* qW raw half [2048,2048] */
#define OF_KWH  (OF_QWH + 2048 * 2048)      /* kW raw half [2048,2048] */
#define OF_VWT  (OF_KWH + 2048 * 2048)
#define OF_FW1T (OF_VWT + 2048 * 2048)
#define OF_FW2T (OF_FW1T + 2048 * 4096)

// ---------------- helpers ----------------
__device__ __forceinline__ float geluf(float x) {
    return 0.5f * x * (1.0f + erff(x * 0.70710678118654752f));
}
__device__ __forceinline__ uint32_t smem_u32(const void *p) {
    uint32_t a;
    asm("{ .reg .u64 t; cvta.to.shared.u64 t, %1; cvt.u32.u64 %0, t; }" : "=r"(a) : "l"(p));
    return a;
}
__device__ __forceinline__ uint32_t swz128(uint32_t off) {
    return off ^ ((off >> 3) & 0x70u);
}
__device__ __forceinline__ void cp16(uint32_t s, const void *g) {
    asm volatile("cp.async.cg.shared.global [%0], [%1], 16;" :: "r"(s), "l"(g));
}
__device__ __forceinline__ void cp_commit() { asm volatile("cp.async.commit_group;" ::: "memory"); }
template <int N> __device__ __forceinline__ void cp_wait() {
    asm volatile("cp.async.wait_group %0;" :: "n"(N) : "memory");
}
__device__ __forceinline__ void ldsm4(uint32_t *r, uint32_t addr) {
    asm volatile("ldmatrix.sync.aligned.m8n8.x4.shared.b16 {%0,%1,%2,%3}, [%4];"
                 : "=r"(r[0]), "=r"(r[1]), "=r"(r[2]), "=r"(r[3]) : "r"(addr));
}
__device__ __forceinline__ void mma16816(float *c, const uint32_t *a, const uint32_t *b) {
    asm volatile(
        "mma.sync.aligned.m16n8k16.row.col.f32.f16.f16.f32 "
        "{%0,%1,%2,%3}, {%4,%5,%6,%7}, {%8,%9}, {%0,%1,%2,%3};"
        : "+f"(c[0]), "+f"(c[1]), "+f"(c[2]), "+f"(c[3])
        : "r"(a[0]), "r"(a[1]), "r"(a[2]), "r"(a[3]), "r"(b[0]), "r"(b[1]));
}
__device__ __forceinline__ float dot4(float4 a, float4 b) {
    return a.x * b.x + a.y * b.y + a.z * b.z + a.w * b.w;
}

// two-value block reduction (sum); result broadcast to all threads
__device__ __forceinline__ void blockReduce2(float &a, float &b) {
    __shared__ float sa[32], sb[32];
#pragma unroll
    for (int o = 16; o; o >>= 1) {
        a += __shfl_xor_sync(0xFFFFFFFFu, a, o);
        b += __shfl_xor_sync(0xFFFFFFFFu, b, o);
    }
    const int lane = threadIdx.x & 31, w = threadIdx.x >> 5;
    const int nw = blockDim.x >> 5;
    if (nw > 1) {
        if (lane == 0) { sa[w] = a; sb[w] = b; }
        __syncthreads();
        a = (lane < nw) ? sa[lane] : 0.0f;
        b = (lane < nw) ? sb[lane] : 0.0f;
#pragma unroll
        for (int o = 16; o; o >>= 1) {
            a += __shfl_xor_sync(0xFFFFFFFFu, a, o);
            b += __shfl_xor_sync(0xFFFFFFFFu, b, o);
        }
        __syncthreads();
    }
}

// ---------------- weight transpose + f32->f16: in[K,N] -> out[N,K] --------
__global__ void transp(const float *__restrict__ in, __half *__restrict__ out,
                       int K, int N) {
    __shared__ float t[32][33];
    const int n0 = blockIdx.x * 32, k0 = blockIdx.y * 32;
#pragma unroll
    for (int i = threadIdx.y; i < 32; i += 8)
        t[i][threadIdx.x] = in[(size_t)(k0 + i) * N + n0 + threadIdx.x];
    __syncthreads();
#pragma unroll
    for (int i = threadIdx.y; i < 32; i += 8)
        out[(size_t)(n0 + i) * K + k0 + threadIdx.x] =
            __float2half_rn(t[threadIdx.x][i]);
}

// ---------------- f32 -> f16 convert ----------------
__global__ void cvt_half(const float4 *__restrict__ in, __half2 *__restrict__ out,
                         int n4) {
    int i = blockIdx.x * blockDim.x + threadIdx.x;
    if (i < n4) {
        float4 v = in[i];
        out[2 * i]     = __floats2half2_rn(v.x, v.y);
        out[2 * i + 1] = __floats2half2_rn(v.z, v.w);
    }
}

// ---------------- u = kW@qb, w = qW@kb, c = qb.kb ----------------
__global__ __launch_bounds__(256) void vec_uwc(
    const float *__restrict__ qW, const float *__restrict__ kW,
    const float *__restrict__ qb, const float *__restrict__ kb,
    float *__restrict__ u, float *__restrict__ w, float *__restrict__ c)
{
    const int r = blockIdx.x, t = threadIdx.x;
    float s = 0.0f, dummy = 0.0f;
    if (r < ND) {
        const float4 *row = (const float4 *)(kW + (size_t)r * ND);
        const float4 *v = (const float4 *)qb;
#pragma unroll
        for (int p = 0; p < 2; p++) s += dot4(row[t + p * 256], v[t + p * 256]);
        blockReduce2(s, dummy);
        if (t == 0) u[r] = s;
    } else if (r < 2 * ND) {
        const float4 *row = (const float4 *)(qW + (size_t)(r - ND) * ND);
        const float4 *v = (const float4 *)kb;
#pragma unroll
        for (int p = 0; p < 2; p++) s += dot4(row[t + p * 256], v[t + p * 256]);
        blockReduce2(s, dummy);
        if (t == 0) w[r - ND] = s;
    } else {
        const float4 *a = (const float4 *)qb;
        const float4 *v = (const float4 *)kb;
#pragma unroll
        for (int p = 0; p < 2; p++) s += dot4(a[t + p * 256], v[t + p * 256]);
        blockReduce2(s, dummy);
        if (t == 0) *c = s;
    }
}

// ---------------- fp16 GEMM: C = concat_K(A1,A2) @ WT^T + bias -------------
// CTA tile 128x256, K chunk 64, 3-stage cp.async pipeline, warp tile 64x64.
#define GT_M 128
#define GT_N 256
#define GKH 64
#define SMA_SZ (GT_M * GKH * 2)         // 16384
#define SMB_SZ (GT_N * GKH * 2)         // 32768
#define STAGE_SZ (SMA_SZ + SMB_SZ)      // 49152
#define NSTAGE 3
#define SM_TOTAL (1024 + NSTAGE * STAGE_SZ)  // 148480

template <int EPI>
__global__ __launch_bounds__(256, 1) void tgemm(
    const __half *__restrict__ A1, const __half *__restrict__ A2,
    const __half *__restrict__ WT, const float *__restrict__ bias,
    float *__restrict__ C, __half *__restrict__ Ch,
    int M, int N, int K1, int K2,
    const float *__restrict__ e1, const float *__restrict__ e2)
{
    extern __shared__ char smem[];
    const uint32_t sb = smem_u32(smem);
    const uint32_t tile0 = (sb + 1023) & ~1023u;
    const int tid = threadIdx.x;
    const int wid = tid >> 5, lane = tid & 31;
    const size_t rowBase = (size_t)blockIdx.y * GT_M;
    const size_t colBase = (size_t)blockIdx.x * GT_N;
    const int K = K1 + K2;
    const int niter = K / GKH;

    const int warpM = (wid >> 2) * 64, warpN = (wid & 3) * 64;

    // cp.async chunk mapping: A 4 chunks/thread, B 8 chunks/thread
    uint32_t aoff[4], boff[8];
    const __half *pA1[4], *pA2[4], *pB[8];
#pragma unroll
    for (int i = 0; i < 4; i++) {
        int c = tid + i * 256, r = c >> 3, k16 = c & 7;
        aoff[i] = swz128((uint32_t)(r * 128 + k16 * 16));
        pA1[i] = A1 + (rowBase + r) * (size_t)K1 + k16 * 8;
        pA2[i] = A2 + (rowBase + r) * (size_t)K2 + k16 * 8 - K1;
    }
#pragma unroll
    for (int i = 0; i < 8; i++) {
        int c = tid + i * 256, r = c >> 3, k16 = c & 7;
        boff[i] = SMA_SZ + swz128((uint32_t)(r * 128 + k16 * 16));
        pB[i] = WT + (colBase + r) * (size_t)K + k16 * 8;
    }

    // ldmatrix per-lane base addresses (swizzle pre-applied, column 0)
    uint32_t aBase[4];
    {
        uint32_t khiA = ((lane >> 4) & 1) * 16;
#pragma unroll
        for (int mt = 0; mt < 4; mt++) {
            int r = warpM + mt * 16 + (lane & 15);
            aBase[mt] = ((uint32_t)(r * 128 + ((r & 7) << 4))) ^ khiA;
        }
    }
    uint32_t bBase[4];
    {
        uint32_t khiB = ((lane >> 3) & 1) * 16;
#pragma unroll
        for (int p = 0; p < 4; p++) {
            int r = warpN + p * 16 + ((lane >> 4) & 1) * 8 + (lane & 7);
            bBase[p] = ((uint32_t)(r * 128 + ((r & 7) << 4))) ^ khiB;
        }
    }

    float acc[4][8][4];
#pragma unroll
    for (int mt = 0; mt < 4; mt++)
#pragma unroll
        for (int nt = 0; nt < 8; nt++)
#pragma unroll
            for (int j = 0; j < 4; j++) acc[mt][nt][j] = 0.0f;

    // stage loader
    auto load_stage = [&](int st, int kg) {
        const uint32_t tb = tile0 + st * STAGE_SZ;
        const bool s1 = kg < K1;
#pragma unroll
        for (int i = 0; i < 4; i++)
            cp16(tb + aoff[i], (s1 ? pA1[i] : pA2[i]) + kg);
#pragma unroll
        for (int i = 0; i < 8; i++) cp16(tb + boff[i], pB[i] + kg);
    };

    // prologue: stages 0,1
    load_stage(0, 0); cp_commit();
    if (niter > 1) load_stage(1, GKH);
    cp_commit();

    for (int it = 0; it < niter; ++it) {
        cp_wait<1>();
        __syncthreads();
        if (it + 2 < niter) load_stage((it + 2) % NSTAGE, (it + 2) * GKH);
        cp_commit();
        const uint32_t tA = tile0 + (it % NSTAGE) * STAGE_SZ;
        const uint32_t tB = tA + SMA_SZ;
#pragma unroll
        for (int k16 = 0; k16 < GKH / 16; ++k16) {
            const uint32_t kb2 = k16 * 32;
            uint32_t a[4][4];
#pragma unroll
            for (int mt = 0; mt < 4; mt++) ldsm4(a[mt], tA + (aBase[mt] ^ kb2));
            uint32_t bf[4][4];
#pragma unroll
            for (int p = 0; p < 4; p++) ldsm4(bf[p], tB + (bBase[p] ^ kb2));
#pragma unroll
            for (int mt = 0; mt < 4; mt++)
#pragma unroll
                for (int p = 0; p < 4; p++) {
                    mma16816(acc[mt][2 * p], a[mt], &bf[p][0]);
                    mma16816(acc[mt][2 * p + 1], a[mt], &bf[p][2]);
                }
        }
    }

    // epilogue
#pragma unroll
    for (int mt = 0; mt < 4; mt++) {
#pragma unroll
        for (int hf = 0; hf < 2; hf++) {
            const size_t m = rowBase + warpM + mt * 16 + (lane >> 2) + hf * 8;
            const size_t crow = m * (size_t)N;
#pragma unroll
            for (int nt = 0; nt < 8; nt++) {
                const size_t c0 = colBase + warpN + nt * 8 + (lane & 3) * 2;
                float v0 = acc[mt][nt][hf * 2 + 0] + bias[c0];
                float v1 = acc[mt][nt][hf * 2 + 1] + bias[c0 + 1];
                if (EPI == 1) { v0 = geluf(v0); v1 = geluf(v1); }
                if (EPI == 2) {
                    float s0 = 1.0f / (1.0f + expf(-v0));
                    float s1 = 1.0f / (1.0f + expf(-v1));
                    v0 = s0 * e1[crow + c0] + (1.0f - s0) * e2[crow + c0];
                    v1 = s1 * e1[crow + c0 + 1] + (1.0f - s1) * e2[crow + c0 + 1];
                }
                if (C) *(float2 *)(C + crow + c0) = make_float2(v0, v1);
                if (Ch) *(__half2 *)(Ch + crow + c0) = __floats2half2_rn(v0, v1);
            }
        }
    }
}

// ---------------- LN + exact GELU -> half out ----------------
__global__ void ln_gelu_h(const float *__restrict__ x, const float *__restrict__ g,
                          const float *__restrict__ b, __half *__restrict__ xh, int N)
{
    const size_t row = blockIdx.x;
    const float4 *xr = (const float4 *)(x + row * (size_t)N);
    const int t = threadIdx.x;
    float4 v = xr[t];
    float s = v.x + v.y + v.z + v.w;
    float sq = v.x * v.x + v.y * v.y + v.z * v.z + v.w * v.w;
    blockReduce2(s, sq);
    const float invN = 1.0f / (float)N;
    float mu = s * invN;
    float var = sq * invN - mu * mu;
    float rs = rsqrtf(var + LNEPS);
    float4 gv = ((const float4 *)g)[t];
    float4 bv = ((const float4 *)b)[t];
    v.x = geluf((v.x - mu) * rs * gv.x + bv.x);
    v.y = geluf((v.y - mu) * rs * gv.y + bv.y);
    v.z = geluf((v.z - mu) * rs * gv.z + bv.z);
    v.w = geluf((v.w - mu) * rs * gv.w + bv.w);
    __half2 *ho = (__half2 *)(xh + row * (size_t)N);
    ho[2 * t] = __floats2half2_rn(v.x, v.y);
    ho[2 * t + 1] = __floats2half2_rn(v.z, v.w);
}

// ---------------- scores + softmax + v-mix (gfM half in, mix overwrites) ---
__global__ __launch_bounds__(256) void scores_mix(
    const __half *__restrict__ gfMh, const float *__restrict__ f1,
    const float *__restrict__ f2, const float *__restrict__ gf,
    const float *__restrict__ uvec, const float *__restrict__ wvec,
    const float *__restrict__ cscal, __half *__restrict__ mixh)
{
    const size_t base4 = (size_t)blockIdx.x * (ND / 4);
    const int t = threadIdx.x;
    float4 f1v[2], f2v[2];
    float d1 = 0, d2 = 0, d3 = 0, d4 = 0, d5 = 0, dummy = 0;
    const __half2 *gm = (const __half2 *)gfMh + base4 * 2;
#pragma unroll
    for (int p = 0; p < 2; p++) {
        int idx = t + p * 256;
        float2 m0 = __half22float2(gm[2 * idx]);
        float2 m1 = __half22float2(gm[2 * idx + 1]);
        float4 m = make_float4(m0.x, m0.y, m1.x, m1.y);
        f1v[p] = ((const float4 *)f1)[base4 + idx];
        f2v[p] = ((const float4 *)f2)[base4 + idx];
        float4 g = ((const float4 *)gf)[base4 + idx];
        float4 uu = ((const float4 *)uvec)[idx];
        float4 ww = ((const float4 *)wvec)[idx];
        d1 += dot4(m, f1v[p]);
        d2 += dot4(m, f2v[p]);
        d3 += dot4(f1v[p], uu);
        d4 += dot4(f2v[p], uu);
        d5 += dot4(g, ww);
    }
    blockReduce2(d1, d2);
    blockReduce2(d3, d4);
    blockReduce2(d5, dummy);
    const float c = *cscal;
    float s1 = (d1 + d3 + d5 + c) * (1.0f / SQRT_D);
    float s2 = (d2 + d4 + d5 + c) * (1.0f / SQRT_D);
    float mx = fmaxf(s1, s2);
    float e1v = expf(s1 - mx), e2v = expf(s2 - mx);
    float w1 = e1v / (e1v + e2v), w2 = 1.0f - w1;
    __half2 *ho = (__half2 *)(mixh) + base4 * 2;
#pragma unroll
    for (int p = 0; p < 2; p++) {
        int idx = t + p * 256;
        float4 a = f1v[p], b = f2v[p];
        ho[2 * idx] = __floats2half2_rn(w1 * a.x + w2 * b.x, w1 * a.y + w2 * b.y);
        ho[2 * idx + 1] = __floats2half2_rn(w1 * a.z + w2 * b.z, w1 * a.w + w2 * b.w);
    }
}

// ---------------- gated = LN(gf+attn); res1 = LN(gated+f1) ----------------
__global__ __launch_bounds__(256) void post_ln(
    const float *__restrict__ gf, const float *__restrict__ attn,
    const float *__restrict__ f1,
    const float *__restrict__ alng, const float *__restrict__ alnb,
    const float *__restrict__ ln1g, const float *__restrict__ ln1b,
    float *__restrict__ out)
{
    const size_t base4 = (size_t)blockIdx.x * (ND / 4);
    const int t = threadIdx.x;
    float4 xv[2];
    float s = 0.0f, sq = 0.0f;
#pragma unroll
    for (int p = 0; p < 2; p++) {
        int idx = t + p * 256;
        float4 g = ((const float4 *)gf)[base4 + idx];
        float4 a = ((const float4 *)attn)[base4 + idx];
        float4 x;
        x.x = g.x + a.x; x.y = g.y + a.y; x.z = g.z + a.z; x.w = g.w + a.w;
        xv[p] = x;
        s += x.x + x.y + x.z + x.w;
        sq += x.x * x.x + x.y * x.y + x.z * x.z + x.w * x.w;
    }
    blockReduce2(s, sq);
    const float invD = 1.0f / (float)ND;
    float mu = s * invD;
    float var = sq * invD - mu * mu;
    float rs = rsqrtf(var + LNEPS);

    float4 yv[2];
    float s3 = 0.0f, sq3 = 0.0f;
#pragma unroll
    for (int p = 0; p < 2; p++) {
        int idx = t + p * 256;
        float4 gv = ((const float4 *)alng)[idx];
        float4 bv = ((const float4 *)alnb)[idx];
        float4 fv = ((const float4 *)f1)[base4 + idx];
        float4 x = xv[p], y;
        y.x = (x.x - mu) * rs * gv.x + bv.x + fv.x;
        y.y = (x.y - mu) * rs * gv.y + bv.y + fv.y;
        y.z = (x.z - mu) * rs * gv.z + bv.z + fv.z;
        y.w = (x.w - mu) * rs * gv.w + bv.w + fv.w;
        yv[p] = y;
        s3 += y.x + y.y + y.z + y.w;
        sq3 += y.x * y.x + y.y * y.y + y.z * y.z + y.w * y.w;
    }
    blockReduce2(s3, sq3);
    float mu2 = s3 * invD;
    float var2 = sq3 * invD - mu2 * mu2;
    float rs2 = rsqrtf(var2 + LNEPS);
#pragma unroll
    for (int p = 0; p < 2; p++) {
        int idx = t + p * 256;
        float4 gv = ((const float4 *)ln1g)[idx];
        float4 bv = ((const float4 *)ln1b)[idx];
        float4 y = yv[p], o;
        o.x = (y.x - mu2) * rs2 * gv.x + bv.x;
        o.y = (y.y - mu2) * rs2 * gv.y + bv.y;
        o.z = (y.z - mu2) * rs2 * gv.z + bv.z;
        o.w = (y.w - mu2) * rs2 * gv.w + bv.w;
        ((float4 *)out)[base4 + idx] = o;
    }
}

// ---------------- aspect BN ----------------
__global__ void bn_count(const int *__restrict__ ids) {
    __shared__ int c[NA];
    if (threadIdx.x < NA) c[threadIdx.x] = 0;
    __syncthreads();
    for (int i = threadIdx.x; i < NB; i += blockDim.x) atomicAdd(&c[ids[i]], 1);
    __syncthreads();
    if (threadIdx.x < NA) g_cnt[threadIdx.x] = c[threadIdx.x];
}

__global__ __launch_bounds__(256) void bn_stats(const float *__restrict__ x,
                                                const int *__restrict__ ids)
{
    __shared__ float ssum[NA][32], ssq[NA][32];
    const int lane = threadIdx.x & 31;
    const int stripe = threadIdx.x >> 5;
    const int c = blockIdx.x * 32 + lane;
    if (stripe == 0) {
#pragma unroll
        for (int a = 0; a < NA; a++) { ssum[a][lane] = 0.0f; ssq[a][lane] = 0.0f; }
    }
    __syncthreads();
    float s0 = 0, s1 = 0, s2 = 0, q0 = 0, q1 = 0, q2 = 0;
#pragma unroll 4
    for (int r = stripe; r < NB; r += 8) {
        int a = ids[r];
        float v = x[(size_t)r * ND + c];
        float vv = v * v;
        if (a == 0) { s0 += v; q0 += vv; }
        else if (a == 1) { s1 += v; q1 += vv; }
        else { s2 += v; q2 += vv; }
    }
    atomicAdd(&ssum[0][lane], s0); atomicAdd(&ssq[0][lane], q0);
    atomicAdd(&ssum[1][lane], s1); atomicAdd(&ssq[1][lane], q1);
    atomicAdd(&ssum[2][lane], s2); atomicAdd(&ssq[2][lane], q2);
    __syncthreads();
    if (stripe < NA) {
        g_bnsum[stripe * ND + c] = ssum[stripe][lane];
        g_bnsq[stripe * ND + c] = ssq[stripe][lane];
    }
}

// BN apply -> half only (for FFN input)
__global__ void bn_apply(const float *__restrict__ x, const int *__restrict__ ids,
                         const float *__restrict__ bng, const float *__restrict__ bnb,
                         __half *__restrict__ outh)
{
    const int i = blockIdx.x * blockDim.x + threadIdx.x;
    const int row = i >> 9;
    const int c4 = i & 511;
    const int a = ids[row];
    const int cnt = g_cnt[a];
    float4 v = ((const float4 *)x)[i];
    if (cnt > 1) {
        const float fc = (float)cnt;
        const int cb4 = (a * ND) / 4 + c4;
        float4 sm = ((const float4 *)g_bnsum)[cb4];
        float4 sc = ((const float4 *)g_bnsq)[cb4];
        float4 gv = ((const float4 *)bng)[cb4];
        float4 bv = ((const float4 *)bnb)[cb4];
        float m, vr;
        m = sm.x / fc; vr = sc.x / fc - m * m; v.x = (v.x - m) * rsqrtf(vr + LNEPS) * gv.x + bv.x;
        m = sm.y / fc; vr = sc.y / fc - m * m; v.y = (v.y - m) * rsqrtf(vr + LNEPS) * gv.y + bv.y;
        m = sm.z / fc; vr = sc.z / fc - m * m; v.z = (v.z - m) * rsqrtf(vr + LNEPS) * gv.z + bv.z;
        m = sm.w / fc; vr = sc.w / fc - m * m; v.w = (v.w - m) * rsqrtf(vr + LNEPS) * gv.w + bv.w;
    }
    __half2 *ho = (__half2 *)outh;
    ho[2 * i] = __floats2half2_rn(v.x, v.y);
    ho[2 * i + 1] = __floats2half2_rn(v.z, v.w);
}

// ---------------- final: out = LN(ffn2 + BN(res1)) ----------------
__global__ __launch_bounds__(256) void ln_residual_bn(
    const float *__restrict__ x, const float *__restrict__ res1,
    const int *__restrict__ ids,
    const float *__restrict__ bng, const float *__restrict__ bnb,
    const float *__restrict__ g, const float *__restrict__ b,
    float *__restrict__ out)
{
    const size_t row = blockIdx.x;
    const size_t base4 = row * (ND / 4);
    const int t = threadIdx.x;
    const int a = ids[row];
    const int cnt = g_cnt[a];
    const float fc = (float)cnt;
    const bool donorm = cnt > 1;
    float4 v[2];
    float s = 0.0f, sq = 0.0f;
#pragma unroll
    for (int p = 0; p < 2; p++) {
        int idx = t + p * 256;
        float4 r = ((const float4 *)res1)[base4 + idx];
        if (donorm) {
            const int cb4 = (a * ND) / 4 + idx;
            float4 sm = ((const float4 *)g_bnsum)[cb4];
            float4 sc = ((const float4 *)g_bnsq)[cb4];
            float4 gv = ((const float4 *)bng)[cb4];
            float4 bv = ((const float4 *)bnb)[cb4];
            float m, vr;
            m = sm.x / fc; vr = sc.x / fc - m * m; r.x = (r.x - m) * rsqrtf(vr + LNEPS) * gv.x + bv.x;
            m = sm.y / fc; vr = sc.y / fc - m * m; r.y = (r.y - m) * rsqrtf(vr + LNEPS) * gv.y + bv.y;
            m = sm.z / fc; vr = sc.z / fc - m * m; r.z = (r.z - m) * rsqrtf(vr + LNEPS) * gv.z + bv.z;
            m = sm.w / fc; vr = sc.w / fc - m * m; r.w = (r.w - m) * rsqrtf(vr + LNEPS) * gv.w + bv.w;
        }
        float4 xv = ((const float4 *)x)[base4 + idx];
        r.x += xv.x; r.y += xv.y; r.z += xv.z; r.w += xv.w;
        v[p] = r;
        s += r.x + r.y + r.z + r.w;
        sq += r.x * r.x + r.y * r.y + r.z * r.z + r.w * r.w;
    }
    blockReduce2(s, sq);
    const float invD = 1.0f / (float)ND;
    float mu = s * invD;
    float var = sq * invD - mu * mu;
    float rs = rsqrtf(var + LNEPS);
#pragma unroll
    for (int p = 0; p < 2; p++) {
        int idx = t + p * 256;
        float4 gv = ((const float4 *)g)[idx];
        float4 bv = ((const float4 *)b)[idx];
        float4 a2 = v[p], o;
        o.x = (a2.x - mu) * rs * gv.x + bv.x;
        o.y = (a2.y - mu) * rs * gv.y + bv.y;
        o.z = (a2.z - mu) * rs * gv.z + bv.z;
        o.w = (a2.w - mu) * rs * gv.w + bv.w;
        ((float4 *)out)[base4 + idx] = o;
    }
}

// ---------------- launch ----------------
extern "C" void kernel_launch(void *const *d_in, const int *in_sizes, int n_in,
                              void *d_out, int out_size)
{
    const float *f1 = (const float *)d_in[0];
    const float *f2 = (const float *)d_in[1];
    const int *ids = (const int *)d_in[2];
    const float *gW1 = (const float *)d_in[3], *gb1 = (const float *)d_in[4];
    const float *gl1g = (const float *)d_in[5], *gl1b = (const float *)d_in[6];
    const float *gW2 = (const float *)d_in[7], *gb2 = (const float *)d_in[8];
    const float *gl2g = (const float *)d_in[9], *gl2b = (const float *)d_in[10];
    const float *gW3 = (const float *)d_in[11], *gb3 = (const float *)d_in[12];
    const float *qW = (const float *)d_in[13], *qb = (const float *)d_in[14];
    const float *kW = (const float *)d_in[15], *kb = (const float *)d_in[16];
    const float *vW = (const float *)d_in[17], *vb = (const float *)d_in[18];
    const float *alng = (const float *)d_in[19], *alnb = (const float *)d_in[20];
    const float *bng = (const float *)d_in[21], *bnb = (const float *)d_in[22];
    const float *ln1g = (const float *)d_in[23], *ln1b = (const float *)d_in[24];
    const float *fW1 = (const float *)d_in[25], *fb1 = (const float *)d_in[26];
    const float *fW2 = (const float *)d_in[27], *fb2 = (const float *)d_in[28];
    const float *ln2g = (const float *)d_in[29], *ln2b = (const float *)d_in[30];
    float *out = (float *)d_out;

    float *h1, *h2, *gf, *q, *attn, *res1, *uv, *wv, *cv, *zb;
    __half *f1h, *f2h, *h1h, *h2h, *gfh, *mixh, *nrmh, *midh, *wth;
    cudaGetSymbolAddress((void **)&h1, g_h1);
    cudaGetSymbolAddress((void **)&h2, g_h2);
    cudaGetSymbolAddress((void **)&gf, g_gf);
    cudaGetSymbolAddress((void **)&q, g_q);
    cudaGetSymbolAddress((void **)&attn, g_attn);
    cudaGetSymbolAddress((void **)&res1, g_res1);
    cudaGetSymbolAddress((void **)&uv, g_u);
    cudaGetSymbolAddress((void **)&wv, g_w);
    cudaGetSymbolAddress((void **)&cv, g_c);
    cudaGetSymbolAddress((void **)&zb, g_zero);
    cudaGetSymbolAddress((void **)&f1h, g_f1h);
    cudaGetSymbolAddress((void **)&f2h, g_f2h);
    cudaGetSymbolAddress((void **)&h1h, g_h1h);
    cudaGetSymbolAddress((void **)&h2h, g_h2h);
    cudaGetSymbolAddress((void **)&gfh, g_gfh);
    cudaGetSymbolAddress((void **)&mixh, g_mixh);
    cudaGetSymbolAddress((void **)&nrmh, g_nrmh);
    cudaGetSymbolAddress((void **)&midh, g_midh);
    cudaGetSymbolAddress((void **)&wth, g_wth);

    cudaFuncSetAttribute(tgemm<0>, cudaFuncAttributeMaxDynamicSharedMemorySize, SM_TOTAL);
    cudaFuncSetAttribute(tgemm<1>, cudaFuncAttributeMaxDynamicSharedMemorySize, SM_TOTAL);
    cudaFuncSetAttribute(tgemm<2>, cudaFuncAttributeMaxDynamicSharedMemorySize, SM_TOTAL);

    // side stream for independent preprocessing (fork/join via events; capture-legal)
    cudaStream_t s2;
    cudaStreamCreateWithFlags(&s2, cudaStreamNonBlocking);
    cudaEvent_t evFork, evJoin;
    cudaEventCreateWithFlags(&evFork, cudaEventDisableTiming);
    cudaEventCreateWithFlags(&evJoin, cudaEventDisableTiming);

    dim3 tb(32, 8);
    cudaEventRecord(evFork, 0);
    cudaStreamWaitEvent(s2, evFork, 0);
    // ---- side stream: everything not needed until gfM / attn / BN / FFN ----
    cvt_half<<<(ND * ND / 4) / 256, 256, 0, s2>>>((const float4 *)qW, (__half2 *)(wth + OF_QWH), ND * ND / 4);
    cvt_half<<<(ND * ND / 4) / 256, 256, 0, s2>>>((const float4 *)kW, (__half2 *)(wth + OF_KWH), ND * ND / 4);
    transp<<<dim3(2048 / 32, 2048 / 32), tb, 0, s2>>>(vW, wth + OF_VWT, 2048, 2048);
    transp<<<dim3(4096 / 32, 2048 / 32), tb, 0, s2>>>(fW1, wth + OF_FW1T, 2048, 4096);
    transp<<<dim3(2048 / 32, 4096 / 32), tb, 0, s2>>>(fW2, wth + OF_FW2T, 4096, 2048);
    vec_uwc<<<2 * ND + 1, 256, 0, s2>>>(qW, kW, qb, kb, uv, wv, cv);
    bn_count<<<1, 256, 0, s2>>>(ids);
    // MT = kW @ qW^T (half out), stored in midh (free until FFN)
    tgemm<0><<<dim3(ND / GT_N, ND / GT_M), 256, SM_TOTAL, s2>>>(
        wth + OF_KWH, wth + OF_KWH, wth + OF_QWH, zb, nullptr, midh,
        ND, ND, ND, 0, nullptr, nullptr);
    cudaEventRecord(evJoin, s2);

    // ---- main stream: gate MLP chain ----
    transp<<<dim3(512 / 32, 4096 / 32), tb>>>(gW1, wth + OF_GW1T, 4096, 512);
    transp<<<dim3(256 / 32, 512 / 32), tb>>>(gW2, wth + OF_GW2T, 512, 256);
    transp<<<dim3(2048 / 32, 256 / 32), tb>>>(gW3, wth + OF_GW3T, 256, 2048);
    cvt_half<<<(NB * ND / 4) / 256, 256>>>((const float4 *)f1, (__half2 *)f1h, NB * ND / 4);
    cvt_half<<<(NB * ND / 4) / 256, 256>>>((const float4 *)f2, (__half2 *)f2h, NB * ND / 4);

    const dim3 gG1(NH / GT_N, NB / GT_M);        // 2 x 64
    const dim3 gG2((NH / 2) / GT_N, NB / GT_M);  // 1 x 64
    const dim3 gD(ND / GT_N, NB / GT_M);         // 8 x 64
    const dim3 g2D((2 * ND) / GT_N, NB / GT_M);  // 16 x 64

    tgemm<0><<<gG1, 256, SM_TOTAL>>>(f1h, f2h, wth + OF_GW1T, gb1, h1, nullptr,
                                     NB, NH, ND, ND, nullptr, nullptr);
    ln_gelu_h<<<NB, NH / 4>>>(h1, gl1g, gl1b, h1h, NH);
    tgemm<0><<<gG2, 256, SM_TOTAL>>>(h1h, h1h, wth + OF_GW2T, gb2, h2, nullptr,
                                     NB, NH / 2, NH, 0, nullptr, nullptr);
    ln_gelu_h<<<NB, (NH / 2) / 4>>>(h2, gl2g, gl2b, h2h, NH / 2);
    tgemm<2><<<gD, 256, SM_TOTAL>>>(h2h, h2h, wth + OF_GW3T, gb3, gf, gfh,
                                    NB, ND, NH / 2, 0, f1, f2);

    // join side stream before anything that needs its outputs
    cudaStreamWaitEvent(0, evJoin, 0);

    // gfM = gf @ M (half out, into mixh; consumed+overwritten in-place by scores_mix)
    tgemm<0><<<gD, 256, SM_TOTAL>>>(gfh, gfh, midh, zb, nullptr, mixh,
                                    NB, ND, ND, 0, nullptr, nullptr);
    scores_mix<<<NB, 256>>>(mixh, f1, f2, gf, uv, wv, cv, mixh);
    // attn = mix @ vW + vb
    tgemm<0><<<gD, 256, SM_TOTAL>>>(mixh, mixh, wth + OF_VWT, vb, attn, nullptr,
                                    NB, ND, ND, 0, nullptr, nullptr);
    post_ln<<<NB, 256>>>(gf, attn, f1, alng, alnb, ln1g, ln1b, res1);
    bn_stats<<<ND / 32, 256>>>(res1, ids);
    bn_apply<<<(NB * ND / 4) / 256, 256>>>(res1, ids, bng, bnb, nrmh);
    // FFN
    tgemm<1><<<g2D, 256, SM_TOTAL>>>(nrmh, nrmh, wth + OF_FW1T, fb1, nullptr, midh,
                                     NB, 2 * ND, ND, 0, nullptr, nullptr);
    tgemm<0><<<gD, 256, SM_TOTAL>>>(midh, midh, wth + OF_FW2T, fb2, q, nullptr,
                                    NB, ND, 2 * ND, 0, nullptr, nullptr);
    ln_residual_bn<<<NB, 256>>>(q, res1, ids, bng, bnb, ln2g, ln2b, out);
}